// round 10
// baseline (speedup 1.0000x reference)
#include <cuda_runtime.h>
#include <cstdint>

#define B_   2
#define LQ   2048
#define LKV  2048
#define D    1024
#define NH   16
#define HD   64
#define MTOT (B_ * LQ)
#define LBH  (B_ * NH)
#define EPS  1e-5f
#define QSZ  4194304           // 4096*1024

// ---------------------------------------------------------------------------
// Scratch (static __device__, allocation-free).
// RULE (learned R3-R6): NEVER pass these as kernel arguments from host —
// host sees the shadow symbol, and GB300 ATS silently dereferences it.
// ---------------------------------------------------------------------------
__device__ float g_WTq[1048576], g_WTk[1048576], g_WTv[1048576], g_WTo[1048576];
__device__ float g_Q[QSZ], g_K[QSZ], g_V[QSZ];   // head-major projections
__device__ float g_ctx[QSZ];
__device__ float g_X[QSZ];

// ---------------------------------------------------------------------------
// helpers
// ---------------------------------------------------------------------------
__device__ __forceinline__ void cp16f(float* s, const float* g) {
    uint32_t sa;
    asm("{ .reg .u64 t; cvta.to.shared.u64 t, %1; cvt.u32.u64 %0, t; }"
        : "=r"(sa) : "l"(s));
    asm volatile("cp.async.cg.shared.global [%0], [%1], 16;" :: "r"(sa), "l"(g) : "memory");
}
#define CP_COMMIT()  asm volatile("cp.async.commit_group;" ::: "memory")
#define CP_WAIT0()   asm volatile("cp.async.wait_group 0;" ::: "memory")
#define CP_WAIT1()   asm volatile("cp.async.wait_group 1;" ::: "memory")

__device__ __forceinline__ uint32_t f2tf32(float f) {
    uint32_t u;
    asm("cvt.rna.tf32.f32 %0, %1;" : "=r"(u) : "f"(f));
    return u;
}

__device__ __forceinline__ void mma_tf32(float* c, uint32_t a0, uint32_t a1,
                                         uint32_t a2, uint32_t a3,
                                         uint32_t b0, uint32_t b1) {
    asm volatile(
        "mma.sync.aligned.m16n8k8.row.col.f32.tf32.tf32.f32 "
        "{%0,%1,%2,%3},{%4,%5,%6,%7},{%8,%9},{%0,%1,%2,%3};"
        : "+f"(c[0]), "+f"(c[1]), "+f"(c[2]), "+f"(c[3])
        : "r"(a0), "r"(a1), "r"(a2), "r"(a3), "r"(b0), "r"(b1));
}

// ---------------------------------------------------------------------------
// tf32 warp-MMA GEMM, 512 threads (16 warps), warp tile 32x32.
// C[M,1024] = A[M,1024] @ W (via WT[N,K] scratch). Block 128x128, BK=32,
// 2-stage cp.async double buffer (73728 B dynamic smem).
// ---------------------------------------------------------------------------
#define KK 1024
#define TSTR 36
#define TILEF (128 * TSTR)

template <int E>
__global__ __launch_bounds__(512, 1) void tgemm(
    const float* __restrict__ Ain,
    int sel, const float* __restrict__ bias, const float* __restrict__ resid)
{
    extern __shared__ float dsm[];
    float* bufA[2] = {dsm,             dsm + TILEF};
    float* bufB[2] = {dsm + 2 * TILEF, dsm + 3 * TILEF};

    const float* B = (sel == 0) ? g_WTq : (sel == 1) ? g_WTk
                   : (sel == 2) ? g_WTv : g_WTo;
    const float* A = (E == 1) ? g_ctx : Ain;

    const int tid  = threadIdx.x;
    const int lane = tid & 31;
    const int w    = tid >> 5;       // 0..15
    const int wm   = w & 3;          // 0..3 (M, 32 rows each)
    const int wn   = w >> 2;         // 0..3 (N, 32 cols each)
    const int m0 = blockIdx.y * 128, n0 = blockIdx.x * 128;

    float c[2][4][4];
#pragma unroll
    for (int i = 0; i < 2; i++)
#pragma unroll
        for (int j = 0; j < 4; j++)
#pragma unroll
            for (int q = 0; q < 4; q++) c[i][j][q] = 0.f;

    const int arow = wm * 32 + (lane >> 2);
    const int acol = lane & 3;
    const int brow = wn * 32 + (lane >> 2);

    auto stage = [&](int bi, int kb) {
        // 128 rows x 8 float4-chunks = 1024 transfers per tile; 512 thr -> 2
#pragma unroll
        for (int i = 0; i < 2; i++) {
            int idx = tid + i * 512;
            int r = idx >> 3, ch = idx & 7;
            int so = r * TSTR + ch * 4;
            cp16f(bufA[bi] + so, A + (size_t)(m0 + r) * KK + kb + ch * 4);
            cp16f(bufB[bi] + so, B + (size_t)(n0 + r) * KK + kb + ch * 4);
        }
    };

    constexpr int nk = KK / 32;
    stage(0, 0);
    CP_COMMIT();

    for (int kt = 0; kt < nk; kt++) {
        if (kt + 1 < nk) {
            stage((kt + 1) & 1, (kt + 1) * 32);
            CP_COMMIT();
            CP_WAIT1();
        } else {
            CP_WAIT0();
        }
        __syncthreads();

        const float* sA = bufA[kt & 1];
        const float* sB = bufB[kt & 1];

#pragma unroll
        for (int ks = 0; ks < 4; ks++) {
            const int ko = ks * 8;
            uint32_t af[2][4], bf[4][2];
#pragma unroll
            for (int mf = 0; mf < 2; mf++) {
                int base = (arow + mf * 16) * TSTR + acol + ko;
                af[mf][0] = f2tf32(sA[base]);
                af[mf][1] = f2tf32(sA[base + 8 * TSTR]);
                af[mf][2] = f2tf32(sA[base + 4]);
                af[mf][3] = f2tf32(sA[base + 8 * TSTR + 4]);
            }
#pragma unroll
            for (int nf = 0; nf < 4; nf++) {
                int bb = (brow + nf * 8) * TSTR + acol + ko;
                bf[nf][0] = f2tf32(sB[bb]);
                bf[nf][1] = f2tf32(sB[bb + 4]);
            }
#pragma unroll
            for (int mf = 0; mf < 2; mf++)
#pragma unroll
                for (int nf = 0; nf < 4; nf++)
                    mma_tf32(c[mf][nf], af[mf][0], af[mf][1], af[mf][2], af[mf][3],
                             bf[nf][0], bf[nf][1]);
        }
        __syncthreads();
    }

#pragma unroll
    for (int mf = 0; mf < 2; mf++)
#pragma unroll
        for (int nf = 0; nf < 4; nf++)
#pragma unroll
            for (int half = 0; half < 2; half++) {
                int m = m0 + wm * 32 + mf * 16 + (lane >> 2) + half * 8;
                int n = n0 + wn * 32 + nf * 8 + (lane & 3) * 2;
                float2 v = make_float2(c[mf][nf][half * 2], c[mf][nf][half * 2 + 1]);

                if constexpr (E == 0) {
                    v.x += __ldg(&bias[n]); v.y += __ldg(&bias[n + 1]);
                    float* outp = (sel == 0) ? g_Q : (sel == 1) ? g_K : g_V;
                    size_t dst = (((size_t)((m >> 11) * NH + (n >> 6))) * LQ + (m & 2047)) * HD + (n & 63);
                    *(float2*)(outp + dst) = v;
                } else {
                    size_t idx = (size_t)m * D + n;
                    float2 r4 = *(const float2*)(resid + idx);
                    v.x += __ldg(&bias[n]) + r4.x;
                    v.y += __ldg(&bias[n + 1]) + r4.y;
                    *(float2*)(g_X + idx) = v;
                }
            }
}

// ---------------------------------------------------------------------------
// fp32 transpose for all 4 weights in one launch (blockIdx.z selects)
// ---------------------------------------------------------------------------
__global__ __launch_bounds__(256) void wtrans4(
    const float* __restrict__ Wq, const float* __restrict__ Wk,
    const float* __restrict__ Wv, const float* __restrict__ Wo)
{
    const int osel = blockIdx.z;
    const float* x = (osel == 0) ? Wq : (osel == 1) ? Wk : (osel == 2) ? Wv : Wo;
    float* y = (osel == 0) ? g_WTq : (osel == 1) ? g_WTk
             : (osel == 2) ? g_WTv : g_WTo;

    __shared__ float t[32][33];
    const int c0 = blockIdx.x * 32, r0 = blockIdx.y * 32;
    const int tx = threadIdx.x, ty = threadIdx.y;

#pragma unroll
    for (int i = 0; i < 4; i++)
        t[ty + 8 * i][tx] = x[(size_t)(r0 + ty + 8 * i) * KK + c0 + tx];
    __syncthreads();
#pragma unroll
    for (int i = 0; i < 4; i++)
        y[(size_t)(c0 + ty + 8 * i) * KK + r0 + tx] = t[tx][ty + 8 * i];
}

// ---------------------------------------------------------------------------
// Tensor-core flash attention (tf32), 512 threads / 16 warps.
// Block: 256 q-rows of one (b,h); each warp 16 q-rows. KV tile 64, 2-stage
// double buffer. Q staged in smem (stride 68, conflict-free frag reads).
// Dynamic smem: Q 256x68 + 2xK 64x68 + 2xV 64x72 = 141312 B.
// ---------------------------------------------------------------------------
#define KSTR 68
#define VSTR 72
#define KTILE (64 * KSTR)
#define VTILE (64 * VSTR)
#define QTILE (256 * KSTR)

__global__ __launch_bounds__(512, 1) void attn_tc()
{
    extern __shared__ float asm_[];
    float* sQ      = asm_;
    float* bufK[2] = {asm_ + QTILE,             asm_ + QTILE + KTILE};
    float* bufV[2] = {asm_ + QTILE + 2 * KTILE, asm_ + QTILE + 2 * KTILE + VTILE};

    const int bh = blockIdx.y;
    const int q0 = blockIdx.x * 256;
    const float* Qp = g_Q + (size_t)bh * LQ * HD;
    const float* Kp = g_K + (size_t)bh * LKV * HD;
    const float* Vp = g_V + (size_t)bh * LKV * HD;

    const int tid  = threadIdx.x;
    const int lane = tid & 31;
    const int w    = tid >> 5;     // 0..15 -> q rows [w*16, w*16+16)
    const int qr   = lane >> 2;
    const int qc   = lane & 3;

    auto stageKV = [&](int bi, int kv0) {
        // 64 rows x 16 chunks = 1024 transfers each for K and V; 512 thr -> 2
#pragma unroll
        for (int i = 0; i < 2; i++) {
            int idx = tid + i * 512;
            int r = idx >> 4, ch = idx & 15;
            cp16f(bufK[bi] + r * KSTR + ch * 4, Kp + (size_t)(kv0 + r) * HD + ch * 4);
            cp16f(bufV[bi] + r * VSTR + ch * 4, Vp + (size_t)(kv0 + r) * HD + ch * 4);
        }
    };

    // stage Q tile: 256 rows x 16 chunks = 4096 transfers; 8 per thread
#pragma unroll
    for (int i = 0; i < 8; i++) {
        int idx = tid + i * 512;
        int r = idx >> 4, ch = idx & 15;
        cp16f(sQ + r * KSTR + ch * 4, Qp + (size_t)(q0 + r) * HD + ch * 4);
    }
    CP_COMMIT();
    stageKV(0, 0);
    CP_COMMIT();

    float o[8][4];
#pragma unroll
    for (int i = 0; i < 8; i++)
#pragma unroll
        for (int j = 0; j < 4; j++) o[i][j] = 0.f;
    float m_i[2] = {-1e30f, -1e30f};
    float l_i[2] = {0.f, 0.f};

    const int srcA = (lane & ~3) | (qc >> 1);
    const int srcB = srcA + 2;
    const int qrow0 = (w * 16 + qr) * KSTR;
    const int qrow1 = (w * 16 + qr + 8) * KSTR;

    constexpr int nt = LKV / 64;
    for (int t = 0; t < nt; t++) {
        if (t + 1 < nt) {
            stageKV((t + 1) & 1, (t + 1) * 64);
            CP_COMMIT();
            CP_WAIT1();
        } else {
            CP_WAIT0();
        }
        __syncthreads();

        const float* sK = bufK[t & 1];
        const float* sV = bufV[t & 1];

        // ---- S = Q K^T (Q frags from smem) ----
        float s[8][4];
#pragma unroll
        for (int i = 0; i < 8; i++)
#pragma unroll
            for (int j = 0; j < 4; j++) s[i][j] = 0.f;

#pragma unroll
        for (int ks = 0; ks < 8; ks++) {
            const int ko = ks * 8;
            uint32_t a0 = f2tf32(sQ[qrow0 + ko + qc]);
            uint32_t a1 = f2tf32(sQ[qrow1 + ko + qc]);
            uint32_t a2 = f2tf32(sQ[qrow0 + ko + qc + 4]);
            uint32_t a3 = f2tf32(sQ[qrow1 + ko + qc + 4]);
#pragma unroll
            for (int nf = 0; nf < 8; nf++) {
                int bb = (nf * 8 + qr) * KSTR + ko + qc;
                uint32_t b0 = f2tf32(sK[bb]);
                uint32_t b1 = f2tf32(sK[bb + 4]);
                mma_tf32(s[nf], a0, a1, a2, a3, b0, b1);
            }
        }

        // ---- online softmax ----
        float mx0 = -1e30f, mx1 = -1e30f;
#pragma unroll
        for (int nf = 0; nf < 8; nf++) {
            s[nf][0] *= 0.125f; s[nf][1] *= 0.125f;
            s[nf][2] *= 0.125f; s[nf][3] *= 0.125f;
            mx0 = fmaxf(mx0, fmaxf(s[nf][0], s[nf][1]));
            mx1 = fmaxf(mx1, fmaxf(s[nf][2], s[nf][3]));
        }
        mx0 = fmaxf(mx0, __shfl_xor_sync(0xffffffffu, mx0, 1));
        mx0 = fmaxf(mx0, __shfl_xor_sync(0xffffffffu, mx0, 2));
        mx1 = fmaxf(mx1, __shfl_xor_sync(0xffffffffu, mx1, 1));
        mx1 = fmaxf(mx1, __shfl_xor_sync(0xffffffffu, mx1, 2));

        float mn0 = fmaxf(m_i[0], mx0), mn1 = fmaxf(m_i[1], mx1);
        float al0 = __expf(m_i[0] - mn0), al1 = __expf(m_i[1] - mn1);
        m_i[0] = mn0; m_i[1] = mn1;

        float rs0 = 0.f, rs1 = 0.f;
#pragma unroll
        for (int nf = 0; nf < 8; nf++) {
            s[nf][0] = __expf(s[nf][0] - mn0);
            s[nf][1] = __expf(s[nf][1] - mn0);
            s[nf][2] = __expf(s[nf][2] - mn1);
            s[nf][3] = __expf(s[nf][3] - mn1);
            rs0 += s[nf][0] + s[nf][1];
            rs1 += s[nf][2] + s[nf][3];
        }
        rs0 += __shfl_xor_sync(0xffffffffu, rs0, 1);
        rs0 += __shfl_xor_sync(0xffffffffu, rs0, 2);
        rs1 += __shfl_xor_sync(0xffffffffu, rs1, 1);
        rs1 += __shfl_xor_sync(0xffffffffu, rs1, 2);
        l_i[0] = l_i[0] * al0 + rs0;
        l_i[1] = l_i[1] * al1 + rs1;

#pragma unroll
        for (int nf = 0; nf < 8; nf++) {
            o[nf][0] *= al0; o[nf][1] *= al0;
            o[nf][2] *= al1; o[nf][3] *= al1;
        }

        // ---- O += P V (P re-laid via shuffles) ----
#pragma unroll
        for (int kg = 0; kg < 8; kg++) {
            uint32_t p0 = f2tf32(s[kg][0]), p1 = f2tf32(s[kg][1]);
            uint32_t p2 = f2tf32(s[kg][2]), p3 = f2tf32(s[kg][3]);
            uint32_t v0 = __shfl_sync(0xffffffffu, p0, srcA);
            uint32_t v1 = __shfl_sync(0xffffffffu, p1, srcA);
            uint32_t v2 = __shfl_sync(0xffffffffu, p2, srcA);
            uint32_t v3 = __shfl_sync(0xffffffffu, p3, srcA);
            uint32_t w0 = __shfl_sync(0xffffffffu, p0, srcB);
            uint32_t w1 = __shfl_sync(0xffffffffu, p1, srcB);
            uint32_t w2 = __shfl_sync(0xffffffffu, p2, srcB);
            uint32_t w3 = __shfl_sync(0xffffffffu, p3, srcB);
            uint32_t a0 = (qc & 1) ? v1 : v0;
            uint32_t a1 = (qc & 1) ? v3 : v2;
            uint32_t a2 = (qc & 1) ? w1 : w0;
            uint32_t a3 = (qc & 1) ? w3 : w2;

            const int ko = kg * 8;
#pragma unroll
            for (int nf = 0; nf < 8; nf++) {
                int bb = (ko + qc) * VSTR + nf * 8 + qr;
                uint32_t b0 = f2tf32(sV[bb]);
                uint32_t b1 = f2tf32(sV[bb + 4 * VSTR]);
                mma_tf32(o[nf], a0, a1, a2, a3, b0, b1);
            }
        }
        __syncthreads();
    }

    // ---- epilogue ----
    const int b = bh >> 4, h = bh & 15;
    const float inv0 = 1.0f / l_i[0], inv1 = 1.0f / l_i[1];
    const int r0 = q0 + w * 16 + qr;
#pragma unroll
    for (int nf = 0; nf < 8; nf++) {
        int col = h * HD + nf * 8 + qc * 2;
        float2 u0 = make_float2(o[nf][0] * inv0, o[nf][1] * inv0);
        float2 u1 = make_float2(o[nf][2] * inv1, o[nf][3] * inv1);
        *(float2*)(g_ctx + (size_t)(b * LQ + r0) * D + col)       = u0;
        *(float2*)(g_ctx + (size_t)(b * LQ + r0 + 8) * D + col)   = u1;
    }
}

// ---------------------------------------------------------------------------
// LayerNorm over last dim (1024)
// ---------------------------------------------------------------------------
__global__ __launch_bounds__(256) void ln_kernel(
    const float* __restrict__ gamma, const float* __restrict__ beta,
    float* __restrict__ out)
{
    __shared__ float red[8];
    const int row = blockIdx.x;
    const int t   = threadIdx.x;
    const float* x = g_X + (size_t)row * D;

    float4 xv = *(const float4*)&x[t << 2];
    float s = xv.x + xv.y + xv.z + xv.w;
#pragma unroll
    for (int m = 16; m > 0; m >>= 1) s += __shfl_xor_sync(0xffffffffu, s, m);
    if ((t & 31) == 0) red[t >> 5] = s;
    __syncthreads();
    float tot = 0.f;
#pragma unroll
    for (int i = 0; i < 8; i++) tot += red[i];
    float mu = tot * (1.0f / D);

    float d0 = xv.x - mu, d1 = xv.y - mu, d2 = xv.z - mu, d3 = xv.w - mu;
    float ss = d0 * d0 + d1 * d1 + d2 * d2 + d3 * d3;
#pragma unroll
    for (int m = 16; m > 0; m >>= 1) ss += __shfl_xor_sync(0xffffffffu, ss, m);
    __syncthreads();
    if ((t & 31) == 0) red[t >> 5] = ss;
    __syncthreads();
    float vtot = 0.f;
#pragma unroll
    for (int i = 0; i < 8; i++) vtot += red[i];
    float inv = rsqrtf(vtot * (1.0f / D) + EPS);

    float4 g  = *(const float4*)&gamma[t << 2];
    float4 be = *(const float4*)&beta[t << 2];
    float4 o;
    o.x = d0 * inv * g.x + be.x;
    o.y = d1 * inv * g.y + be.y;
    o.z = d2 * inv * g.z + be.z;
    o.w = d3 * inv * g.w + be.w;
    *(float4*)&out[(size_t)row * D + (t << 2)] = o;
}

// ---------------------------------------------------------------------------
extern "C" void kernel_launch(void* const* d_in, const int* in_sizes, int n_in,
                              void* d_out, int out_size)
{
    (void)in_sizes; (void)n_in; (void)out_size;
    const float* query     = (const float*)d_in[0];
    const float* key_value = (const float*)d_in[1];
    const float* Wq = (const float*)d_in[2];
    const float* bq = (const float*)d_in[3];
    const float* Wk = (const float*)d_in[4];
    const float* bk = (const float*)d_in[5];
    const float* Wv = (const float*)d_in[6];
    const float* bv = (const float*)d_in[7];
    const float* Wo = (const float*)d_in[8];
    const float* bo = (const float*)d_in[9];
    const float* gamma = (const float*)d_in[10];
    const float* beta  = (const float*)d_in[11];
    float* out = (float*)d_out;

    constexpr int GSM = 4 * TILEF * 4;                         // 73728 B
    constexpr int ASM = (QTILE + 2 * KTILE + 2 * VTILE) * 4;   // 141312 B
    cudaFuncSetAttribute(tgemm<0>, cudaFuncAttributeMaxDynamicSharedMemorySize, GSM);
    cudaFuncSetAttribute(tgemm<1>, cudaFuncAttributeMaxDynamicSharedMemorySize, GSM);
    cudaFuncSetAttribute(attn_tc,  cudaFuncAttributeMaxDynamicSharedMemorySize, ASM);

    // 1. transpose all weights (one launch)
    wtrans4<<<dim3(32, 32, 4), dim3(32, 8)>>>(Wq, Wk, Wv, Wo);

    // 2. Q/K/V projections (tf32 tensor cores, head-major fp32 out)
    dim3 pg(8, 32);
    tgemm<0><<<pg, 512, GSM>>>(query,     0, bq, nullptr);
    tgemm<0><<<pg, 512, GSM>>>(key_value, 1, bk, nullptr);
    tgemm<0><<<pg, 512, GSM>>>(key_value, 2, bv, nullptr);

    // 3. attention (tf32 tensor-core flash, 16 warps, 256-row q tiles)
    attn_tc<<<dim3(LQ / 256, LBH), 512, ASM>>>();

    // 4. output projection + residual
    tgemm<1><<<pg, 512, GSM>>>(nullptr, 3, bo, query);

    // 5. LayerNorm
    ln_kernel<<<MTOT, 256>>>(gamma, beta, out);
}

// round 11
// speedup vs baseline: 1.1653x; 1.1653x over previous
#include <cuda_runtime.h>
#include <cstdint>

#define B_   2
#define LQ   2048
#define LKV  2048
#define D    1024
#define NH   16
#define HD   64
#define MTOT (B_ * LQ)
#define LBH  (B_ * NH)
#define EPS  1e-5f
#define QSZ  4194304           // 4096*1024

// ---------------------------------------------------------------------------
// Scratch (static __device__, allocation-free).
// RULE (learned R3-R6): NEVER pass these as kernel arguments from host —
// host sees the shadow symbol, and GB300 ATS silently dereferences it.
// ---------------------------------------------------------------------------
__device__ float g_WTq[1048576], g_WTk[1048576], g_WTv[1048576], g_WTo[1048576];
__device__ float g_Q[QSZ], g_K[QSZ], g_V[QSZ];   // head-major projections
__device__ float g_ctx[QSZ];
__device__ float g_X[QSZ];

// ---------------------------------------------------------------------------
// helpers
// ---------------------------------------------------------------------------
__device__ __forceinline__ void cp16f(float* s, const float* g) {
    uint32_t sa;
    asm("{ .reg .u64 t; cvta.to.shared.u64 t, %1; cvt.u32.u64 %0, t; }"
        : "=r"(sa) : "l"(s));
    asm volatile("cp.async.cg.shared.global [%0], [%1], 16;" :: "r"(sa), "l"(g) : "memory");
}
#define CP_COMMIT()  asm volatile("cp.async.commit_group;" ::: "memory")
#define CP_WAIT0()   asm volatile("cp.async.wait_group 0;" ::: "memory")

// raw fp32 bits -> tf32 operand (HW truncates mantissa; no cvt instruction)
__device__ __forceinline__ uint32_t rawb(float f) { return __float_as_uint(f); }

__device__ __forceinline__ void mma_tf32(float* c, uint32_t a0, uint32_t a1,
                                         uint32_t a2, uint32_t a3,
                                         uint32_t b0, uint32_t b1) {
    asm volatile(
        "mma.sync.aligned.m16n8k8.row.col.f32.tf32.tf32.f32 "
        "{%0,%1,%2,%3},{%4,%5,%6,%7},{%8,%9},{%0,%1,%2,%3};"
        : "+f"(c[0]), "+f"(c[1]), "+f"(c[2]), "+f"(c[3])
        : "r"(a0), "r"(a1), "r"(a2), "r"(a3), "r"(b0), "r"(b1));
}

// ---------------------------------------------------------------------------
// tf32 warp-MMA GEMM (R8 skeleton: 256 thr, single-buffered, warp 64x32).
// No in-loop cvt: raw fp32 bits go straight to the MMA.
// ---------------------------------------------------------------------------
#define KK 1024
#define TSTR 36

template <int E>
__global__ __launch_bounds__(256, 1) void tgemm(
    const float* __restrict__ Ain,
    int sel, const float* __restrict__ bias, const float* __restrict__ resid)
{
    __shared__ float sA[128 * TSTR];
    __shared__ float sB[128 * TSTR];

    const float* B = (sel == 0) ? g_WTq : (sel == 1) ? g_WTk
                   : (sel == 2) ? g_WTv : g_WTo;
    const float* A = (E == 1) ? g_ctx : Ain;

    const int tid  = threadIdx.x;
    const int lane = tid & 31;
    const int w    = tid >> 5;
    const int wm   = w & 1;
    const int wn   = w >> 1;
    const int m0 = blockIdx.y * 128, n0 = blockIdx.x * 128;

    float c[4][4][4];
#pragma unroll
    for (int i = 0; i < 4; i++)
#pragma unroll
        for (int j = 0; j < 4; j++)
#pragma unroll
            for (int q = 0; q < 4; q++) c[i][j][q] = 0.f;

    const int arow = wm * 64 + (lane >> 2);
    const int acol = lane & 3;
    const int brow = wn * 32 + (lane >> 2);

    for (int kb = 0; kb < KK; kb += 32) {
#pragma unroll
        for (int i = 0; i < 4; i++) {
            int idx = tid + i * 256;
            int r = idx >> 3, ch = idx & 7;
            int so = r * TSTR + ch * 4;
            cp16f(sA + so, A + (size_t)(m0 + r) * KK + kb + ch * 4);
            cp16f(sB + so, B + (size_t)(n0 + r) * KK + kb + ch * 4);
        }
        CP_COMMIT();
        CP_WAIT0();
        __syncthreads();

#pragma unroll
        for (int ks = 0; ks < 4; ks++) {
            const int ko = ks * 8;
            uint32_t af[4][4], bf[4][2];
#pragma unroll
            for (int mf = 0; mf < 4; mf++) {
                int base = (arow + mf * 16) * TSTR + acol + ko;
                af[mf][0] = rawb(sA[base]);
                af[mf][1] = rawb(sA[base + 8 * TSTR]);
                af[mf][2] = rawb(sA[base + 4]);
                af[mf][3] = rawb(sA[base + 8 * TSTR + 4]);
            }
#pragma unroll
            for (int nf = 0; nf < 4; nf++) {
                int bb = (brow + nf * 8) * TSTR + acol + ko;
                bf[nf][0] = rawb(sB[bb]);
                bf[nf][1] = rawb(sB[bb + 4]);
            }
#pragma unroll
            for (int mf = 0; mf < 4; mf++)
#pragma unroll
                for (int nf = 0; nf < 4; nf++)
                    mma_tf32(c[mf][nf], af[mf][0], af[mf][1], af[mf][2], af[mf][3],
                             bf[nf][0], bf[nf][1]);
        }
        __syncthreads();
    }

#pragma unroll
    for (int mf = 0; mf < 4; mf++)
#pragma unroll
        for (int nf = 0; nf < 4; nf++)
#pragma unroll
            for (int half = 0; half < 2; half++) {
                int m = m0 + wm * 64 + mf * 16 + (lane >> 2) + half * 8;
                int n = n0 + wn * 32 + nf * 8 + (lane & 3) * 2;
                float2 v = make_float2(c[mf][nf][half * 2], c[mf][nf][half * 2 + 1]);

                if constexpr (E == 0) {
                    v.x += __ldg(&bias[n]); v.y += __ldg(&bias[n + 1]);
                    float* outp = (sel == 0) ? g_Q : (sel == 1) ? g_K : g_V;
                    size_t dst = (((size_t)((m >> 11) * NH + (n >> 6))) * LQ + (m & 2047)) * HD + (n & 63);
                    *(float2*)(outp + dst) = v;
                } else {
                    size_t idx = (size_t)m * D + n;
                    float2 r4 = *(const float2*)(resid + idx);
                    v.x += __ldg(&bias[n]) + r4.x;
                    v.y += __ldg(&bias[n + 1]) + r4.y;
                    *(float2*)(g_X + idx) = v;
                }
            }
}

// ---------------------------------------------------------------------------
// fp32 transpose for all 4 weights in one launch (blockIdx.z selects)
// ---------------------------------------------------------------------------
__global__ __launch_bounds__(256) void wtrans4(
    const float* __restrict__ Wq, const float* __restrict__ Wk,
    const float* __restrict__ Wv, const float* __restrict__ Wo)
{
    const int osel = blockIdx.z;
    const float* x = (osel == 0) ? Wq : (osel == 1) ? Wk : (osel == 2) ? Wv : Wo;
    float* y = (osel == 0) ? g_WTq : (osel == 1) ? g_WTk
             : (osel == 2) ? g_WTv : g_WTo;

    __shared__ float t[32][33];
    const int c0 = blockIdx.x * 32, r0 = blockIdx.y * 32;
    const int tx = threadIdx.x, ty = threadIdx.y;

#pragma unroll
    for (int i = 0; i < 4; i++)
        t[ty + 8 * i][tx] = x[(size_t)(r0 + ty + 8 * i) * KK + c0 + tx];
    __syncthreads();
#pragma unroll
    for (int i = 0; i < 4; i++)
        y[(size_t)(c0 + ty + 8 * i) * KK + r0 + tx] = t[tx][ty + 8 * i];
}

// ---------------------------------------------------------------------------
// Tensor-core flash attention (R8 skeleton: 256 thr, single-buffered,
// q-tile 128, KV tile 64). No in-loop cvt (raw fp32 bits to MMA).
// ---------------------------------------------------------------------------
#define KSTR 68
#define VSTR 72

__global__ __launch_bounds__(256, 1) void attn_tc()
{
    __shared__ float sK[64 * KSTR];
    __shared__ float sV[64 * VSTR];

    const int bh = blockIdx.y;
    const int q0 = blockIdx.x * 128;
    const float* Qp = g_Q + (size_t)bh * LQ * HD;
    const float* Kp = g_K + (size_t)bh * LKV * HD;
    const float* Vp = g_V + (size_t)bh * LKV * HD;

    const int tid  = threadIdx.x;
    const int lane = tid & 31;
    const int w    = tid >> 5;
    const int qr   = lane >> 2;
    const int qc   = lane & 3;

    // ---- load Q fragments (16 rows per warp, 8 k-steps), raw bits ----
    uint32_t qf[8][4];
    {
        const int r0 = q0 + w * 16 + qr;
#pragma unroll
        for (int ks = 0; ks < 8; ks++) {
            int k = ks * 8 + qc;
            qf[ks][0] = rawb(__ldg(Qp + (size_t)r0 * HD + k));
            qf[ks][1] = rawb(__ldg(Qp + (size_t)(r0 + 8) * HD + k));
            qf[ks][2] = rawb(__ldg(Qp + (size_t)r0 * HD + k + 4));
            qf[ks][3] = rawb(__ldg(Qp + (size_t)(r0 + 8) * HD + k + 4));
        }
    }

    float o[8][4];
#pragma unroll
    for (int i = 0; i < 8; i++)
#pragma unroll
        for (int j = 0; j < 4; j++) o[i][j] = 0.f;
    float m_i[2] = {-1e30f, -1e30f};
    float l_i[2] = {0.f, 0.f};

    const int srcA = (lane & ~3) | (qc >> 1);
    const int srcB = srcA + 2;

    for (int kv0 = 0; kv0 < LKV; kv0 += 64) {
#pragma unroll
        for (int i = 0; i < 4; i++) {
            int idx = tid + i * 256;
            int r = idx >> 4, ch = idx & 15;
            cp16f(sK + r * KSTR + ch * 4, Kp + (size_t)(kv0 + r) * HD + ch * 4);
            cp16f(sV + r * VSTR + ch * 4, Vp + (size_t)(kv0 + r) * HD + ch * 4);
        }
        CP_COMMIT();
        CP_WAIT0();
        __syncthreads();

        // ---- S = Q K^T ----
        float s[8][4];
#pragma unroll
        for (int i = 0; i < 8; i++)
#pragma unroll
            for (int j = 0; j < 4; j++) s[i][j] = 0.f;

#pragma unroll
        for (int ks = 0; ks < 8; ks++) {
            const int ko = ks * 8;
#pragma unroll
            for (int nf = 0; nf < 8; nf++) {
                int bb = (nf * 8 + qr) * KSTR + ko + qc;
                uint32_t b0 = rawb(sK[bb]);
                uint32_t b1 = rawb(sK[bb + 4]);
                mma_tf32(s[nf], qf[ks][0], qf[ks][1], qf[ks][2], qf[ks][3], b0, b1);
            }
        }

        // ---- online softmax ----
        float mx0 = -1e30f, mx1 = -1e30f;
#pragma unroll
        for (int nf = 0; nf < 8; nf++) {
            s[nf][0] *= 0.125f; s[nf][1] *= 0.125f;
            s[nf][2] *= 0.125f; s[nf][3] *= 0.125f;
            mx0 = fmaxf(mx0, fmaxf(s[nf][0], s[nf][1]));
            mx1 = fmaxf(mx1, fmaxf(s[nf][2], s[nf][3]));
        }
        mx0 = fmaxf(mx0, __shfl_xor_sync(0xffffffffu, mx0, 1));
        mx0 = fmaxf(mx0, __shfl_xor_sync(0xffffffffu, mx0, 2));
        mx1 = fmaxf(mx1, __shfl_xor_sync(0xffffffffu, mx1, 1));
        mx1 = fmaxf(mx1, __shfl_xor_sync(0xffffffffu, mx1, 2));

        float mn0 = fmaxf(m_i[0], mx0), mn1 = fmaxf(m_i[1], mx1);
        float al0 = __expf(m_i[0] - mn0), al1 = __expf(m_i[1] - mn1);
        m_i[0] = mn0; m_i[1] = mn1;

        float rs0 = 0.f, rs1 = 0.f;
#pragma unroll
        for (int nf = 0; nf < 8; nf++) {
            s[nf][0] = __expf(s[nf][0] - mn0);
            s[nf][1] = __expf(s[nf][1] - mn0);
            s[nf][2] = __expf(s[nf][2] - mn1);
            s[nf][3] = __expf(s[nf][3] - mn1);
            rs0 += s[nf][0] + s[nf][1];
            rs1 += s[nf][2] + s[nf][3];
        }
        rs0 += __shfl_xor_sync(0xffffffffu, rs0, 1);
        rs0 += __shfl_xor_sync(0xffffffffu, rs0, 2);
        rs1 += __shfl_xor_sync(0xffffffffu, rs1, 1);
        rs1 += __shfl_xor_sync(0xffffffffu, rs1, 2);
        l_i[0] = l_i[0] * al0 + rs0;
        l_i[1] = l_i[1] * al1 + rs1;

#pragma unroll
        for (int nf = 0; nf < 8; nf++) {
            o[nf][0] *= al0; o[nf][1] *= al0;
            o[nf][2] *= al1; o[nf][3] *= al1;
        }

        // ---- O += P V (raw-bit P re-laid via shuffles) ----
#pragma unroll
        for (int kg = 0; kg < 8; kg++) {
            uint32_t p0 = rawb(s[kg][0]), p1 = rawb(s[kg][1]);
            uint32_t p2 = rawb(s[kg][2]), p3 = rawb(s[kg][3]);
            uint32_t v0 = __shfl_sync(0xffffffffu, p0, srcA);
            uint32_t v1 = __shfl_sync(0xffffffffu, p1, srcA);
            uint32_t v2 = __shfl_sync(0xffffffffu, p2, srcA);
            uint32_t v3 = __shfl_sync(0xffffffffu, p3, srcA);
            uint32_t w0 = __shfl_sync(0xffffffffu, p0, srcB);
            uint32_t w1 = __shfl_sync(0xffffffffu, p1, srcB);
            uint32_t w2 = __shfl_sync(0xffffffffu, p2, srcB);
            uint32_t w3 = __shfl_sync(0xffffffffu, p3, srcB);
            uint32_t a0 = (qc & 1) ? v1 : v0;
            uint32_t a1 = (qc & 1) ? v3 : v2;
            uint32_t a2 = (qc & 1) ? w1 : w0;
            uint32_t a3 = (qc & 1) ? w3 : w2;

            const int ko = kg * 8;
#pragma unroll
            for (int nf = 0; nf < 8; nf++) {
                int bb = (ko + qc) * VSTR + nf * 8 + qr;
                uint32_t b0 = rawb(sV[bb]);
                uint32_t b1 = rawb(sV[bb + 4 * VSTR]);
                mma_tf32(o[nf], a0, a1, a2, a3, b0, b1);
            }
        }
        __syncthreads();
    }

    // ---- epilogue ----
    const int b = bh >> 4, h = bh & 15;
    const float inv0 = 1.0f / l_i[0], inv1 = 1.0f / l_i[1];
    const int r0 = q0 + w * 16 + qr;
#pragma unroll
    for (int nf = 0; nf < 8; nf++) {
        int col = h * HD + nf * 8 + qc * 2;
        float2 u0 = make_float2(o[nf][0] * inv0, o[nf][1] * inv0);
        float2 u1 = make_float2(o[nf][2] * inv1, o[nf][3] * inv1);
        *(float2*)(g_ctx + (size_t)(b * LQ + r0) * D + col)       = u0;
        *(float2*)(g_ctx + (size_t)(b * LQ + r0 + 8) * D + col)   = u1;
    }
}

// ---------------------------------------------------------------------------
// LayerNorm over last dim (1024)
// ---------------------------------------------------------------------------
__global__ __launch_bounds__(256) void ln_kernel(
    const float* __restrict__ gamma, const float* __restrict__ beta,
    float* __restrict__ out)
{
    __shared__ float red[8];
    const int row = blockIdx.x;
    const int t   = threadIdx.x;
    const float* x = g_X + (size_t)row * D;

    float4 xv = *(const float4*)&x[t << 2];
    float s = xv.x + xv.y + xv.z + xv.w;
#pragma unroll
    for (int m = 16; m > 0; m >>= 1) s += __shfl_xor_sync(0xffffffffu, s, m);
    if ((t & 31) == 0) red[t >> 5] = s;
    __syncthreads();
    float tot = 0.f;
#pragma unroll
    for (int i = 0; i < 8; i++) tot += red[i];
    float mu = tot * (1.0f / D);

    float d0 = xv.x - mu, d1 = xv.y - mu, d2 = xv.z - mu, d3 = xv.w - mu;
    float ss = d0 * d0 + d1 * d1 + d2 * d2 + d3 * d3;
#pragma unroll
    for (int m = 16; m > 0; m >>= 1) ss += __shfl_xor_sync(0xffffffffu, ss, m);
    __syncthreads();
    if ((t & 31) == 0) red[t >> 5] = ss;
    __syncthreads();
    float vtot = 0.f;
#pragma unroll
    for (int i = 0; i < 8; i++) vtot += red[i];
    float inv = rsqrtf(vtot * (1.0f / D) + EPS);

    float4 g  = *(const float4*)&gamma[t << 2];
    float4 be = *(const float4*)&beta[t << 2];
    float4 o;
    o.x = d0 * inv * g.x + be.x;
    o.y = d1 * inv * g.y + be.y;
    o.z = d2 * inv * g.z + be.z;
    o.w = d3 * inv * g.w + be.w;
    *(float4*)&out[(size_t)row * D + (t << 2)] = o;
}

// ---------------------------------------------------------------------------
extern "C" void kernel_launch(void* const* d_in, const int* in_sizes, int n_in,
                              void* d_out, int out_size)
{
    (void)in_sizes; (void)n_in; (void)out_size;
    const float* query     = (const float*)d_in[0];
    const float* key_value = (const float*)d_in[1];
    const float* Wq = (const float*)d_in[2];
    const float* bq = (const float*)d_in[3];
    const float* Wk = (const float*)d_in[4];
    const float* bk = (const float*)d_in[5];
    const float* Wv = (const float*)d_in[6];
    const float* bv = (const float*)d_in[7];
    const float* Wo = (const float*)d_in[8];
    const float* bo = (const float*)d_in[9];
    const float* gamma = (const float*)d_in[10];
    const float* beta  = (const float*)d_in[11];
    float* out = (float*)d_out;

    // 1. transpose all weights (one launch)
    wtrans4<<<dim3(32, 32, 4), dim3(32, 8)>>>(Wq, Wk, Wv, Wo);

    // 2. Q/K/V projections (tf32 tensor cores, head-major fp32 out)
    dim3 pg(8, 32);
    tgemm<0><<<pg, 256>>>(query,     0, bq, nullptr);
    tgemm<0><<<pg, 256>>>(key_value, 1, bk, nullptr);
    tgemm<0><<<pg, 256>>>(key_value, 2, bv, nullptr);

    // 3. attention (tf32 tensor-core flash)
    attn_tc<<<dim3(LQ / 128, LBH), 256>>>();

    // 4. output projection + residual
    tgemm<1><<<pg, 256>>>(nullptr, 3, bo, query);

    // 5. LayerNorm
    ln_kernel<<<MTOT, 256>>>(gamma, beta, out);
}

// round 12
// speedup vs baseline: 1.9639x; 1.6854x over previous
#include <cuda_runtime.h>
#include <cuda_bf16.h>
#include <cstdint>

#define B_   2
#define LQ   2048
#define LKV  2048
#define D    1024
#define NH   16
#define HD   64
#define MTOT (B_ * LQ)
#define LBH  (B_ * NH)
#define EPS  1e-5f
#define QSZ  4194304           // 4096*1024

// ---------------------------------------------------------------------------
// Scratch (static __device__, allocation-free).
// RULE (learned R3-R6): NEVER pass these as kernel arguments from host —
// host sees the shadow symbol, and GB300 ATS silently dereferences it.
// ---------------------------------------------------------------------------
__device__ __nv_bfloat16 g_WTq[1048576], g_WTk[1048576], g_WTv[1048576], g_WTo[1048576];
__device__ __nv_bfloat16 g_Aq[QSZ], g_Akv[QSZ];     // bf16 activations
__device__ __nv_bfloat16 g_Qh[QSZ], g_Kh[QSZ];      // head-major Q,K bf16
__device__ __nv_bfloat16 g_VT[QSZ];                 // V transposed per head [bh][hd][kv]
__device__ __nv_bfloat16 g_ctxh[QSZ];               // ctx bf16
__device__ float g_X[QSZ];                          // pre-LN fp32

// ---------------------------------------------------------------------------
// helpers
// ---------------------------------------------------------------------------
__device__ __forceinline__ void cp16(void* s, const void* g) {
    uint32_t sa;
    asm("{ .reg .u64 t; cvta.to.shared.u64 t, %1; cvt.u32.u64 %0, t; }"
        : "=r"(sa) : "l"(s));
    asm volatile("cp.async.cg.shared.global [%0], [%1], 16;" :: "r"(sa), "l"(g) : "memory");
}
#define CP_COMMIT()  asm volatile("cp.async.commit_group;" ::: "memory")
#define CP_WAIT0()   asm volatile("cp.async.wait_group 0;" ::: "memory")

// pack two fp32 into bf16x2: result = {lo, hi}
__device__ __forceinline__ uint32_t pack_bf2(float lo, float hi) {
    uint32_t r;
    asm("cvt.rn.bf16x2.f32 %0, %1, %2;" : "=r"(r) : "f"(hi), "f"(lo));
    return r;
}

__device__ __forceinline__ void mma_bf16(float* c, uint32_t a0, uint32_t a1,
                                         uint32_t a2, uint32_t a3,
                                         uint32_t b0, uint32_t b1) {
    asm volatile(
        "mma.sync.aligned.m16n8k16.row.col.f32.bf16.bf16.f32 "
        "{%0,%1,%2,%3},{%4,%5,%6,%7},{%8,%9},{%0,%1,%2,%3};"
        : "+f"(c[0]), "+f"(c[1]), "+f"(c[2]), "+f"(c[3])
        : "r"(a0), "r"(a1), "r"(a2), "r"(a3), "r"(b0), "r"(b1));
}

// ---------------------------------------------------------------------------
// bf16 warp-MMA GEMM: C[M,1024] = A @ W  (A bf16 scratch, WT[N,K] bf16).
// Block 128x128, BK=64, 256 thr, warp tile 64x32, single-buffered cp.async.
// Smem: 2 x 128 rows x 36 uint = 36 KB (uint = bf16x2; 32 data + 4 pad).
// E=0: out = g_Qh/g_Kh (bf16 head-major) or g_VT (bf16 transposed) by sel
// E=1: A = g_ctxh; X = A @ Wo + bias + resid -> g_X (fp32)
// ---------------------------------------------------------------------------
#define KK 1024
#define GSTR 36               // uint stride per row (64 bf16 = 32 uint + 4 pad)

template <int E>
__global__ __launch_bounds__(256, 1) void tgemm(
    int asel, int sel, const float* __restrict__ bias, const float* __restrict__ resid)
{
    __shared__ uint32_t sA[128 * GSTR];
    __shared__ uint32_t sB[128 * GSTR];

    const __nv_bfloat16* B = (sel == 0) ? g_WTq : (sel == 1) ? g_WTk
                           : (sel == 2) ? g_WTv : g_WTo;
    const __nv_bfloat16* A = (E == 1) ? g_ctxh : (asel == 0 ? g_Aq : g_Akv);

    const int tid  = threadIdx.x;
    const int lane = tid & 31;
    const int w    = tid >> 5;
    const int wm   = w & 1;
    const int wn   = w >> 1;
    const int m0 = blockIdx.y * 128, n0 = blockIdx.x * 128;
    const int qr = lane >> 2, qc = lane & 3;

    float c[4][4][4];
#pragma unroll
    for (int i = 0; i < 4; i++)
#pragma unroll
        for (int j = 0; j < 4; j++)
#pragma unroll
            for (int q = 0; q < 4; q++) c[i][j][q] = 0.f;

    const int arow = wm * 64 + qr;
    const int brow = wn * 32 + qr;

    for (int kb = 0; kb < KK; kb += 64) {
        // stage A,B: 128 rows x 64 bf16 = 8 chunks of 16B each
#pragma unroll
        for (int i = 0; i < 4; i++) {
            int idx = tid + i * 256;
            int r = idx >> 3, ch = idx & 7;
            int so = r * GSTR + ch * 4;
            cp16(sA + so, A + (size_t)(m0 + r) * KK + kb + ch * 8);
            cp16(sB + so, B + (size_t)(n0 + r) * KK + kb + ch * 8);
        }
        CP_COMMIT();
        CP_WAIT0();
        __syncthreads();

#pragma unroll
        for (int ks = 0; ks < 4; ks++) {         // 4 x k16 = 64
            const int ko = ks * 8;               // uint col
            uint32_t af[4][4], bf[4][2];
#pragma unroll
            for (int mf = 0; mf < 4; mf++) {
                int base = (arow + mf * 16) * GSTR + ko + qc;
                af[mf][0] = sA[base];
                af[mf][1] = sA[base + 8 * GSTR];
                af[mf][2] = sA[base + 4];
                af[mf][3] = sA[base + 8 * GSTR + 4];
            }
#pragma unroll
            for (int nf = 0; nf < 4; nf++) {
                int bb = (brow + nf * 8) * GSTR + ko + qc;
                bf[nf][0] = sB[bb];
                bf[nf][1] = sB[bb + 4];
            }
#pragma unroll
            for (int mf = 0; mf < 4; mf++)
#pragma unroll
                for (int nf = 0; nf < 4; nf++)
                    mma_bf16(c[mf][nf], af[mf][0], af[mf][1], af[mf][2], af[mf][3],
                             bf[nf][0], bf[nf][1]);
        }
        __syncthreads();
    }

    // ---- epilogue ----
#pragma unroll
    for (int mf = 0; mf < 4; mf++)
#pragma unroll
        for (int nf = 0; nf < 4; nf++)
#pragma unroll
            for (int half = 0; half < 2; half++) {
                int m = m0 + wm * 64 + mf * 16 + qr + half * 8;
                int n = n0 + wn * 32 + nf * 8 + qc * 2;
                float vx = c[mf][nf][half * 2]     + __ldg(&bias[n]);
                float vy = c[mf][nf][half * 2 + 1] + __ldg(&bias[n + 1]);

                if constexpr (E == 0) {
                    int bh = (m >> 11) * NH + (n >> 6);
                    int l  = m & 2047;
                    int hd = n & 63;
                    if (sel == 2) {
                        // V: transposed scatter -> g_VT[bh][hd][kv]
                        g_VT[((size_t)bh * 64 + hd) * LKV + l]     = __float2bfloat16(vx);
                        g_VT[((size_t)bh * 64 + hd + 1) * LKV + l] = __float2bfloat16(vy);
                    } else {
                        __nv_bfloat16* outp = (sel == 0) ? g_Qh : g_Kh;
                        *(uint32_t*)(outp + ((size_t)bh * LQ + l) * HD + hd) = pack_bf2(vx, vy);
                    }
                } else {
                    size_t idx = (size_t)m * D + n;
                    float2 r4 = *(const float2*)(resid + idx);
                    *(float2*)(g_X + idx) = make_float2(vx + r4.x, vy + r4.y);
                }
            }
}

// ---------------------------------------------------------------------------
// transpose + fp32->bf16: harness W[K,N] -> g_WT*[N,K] bf16 (device-side sel)
// ---------------------------------------------------------------------------
__global__ __launch_bounds__(256) void wtrans4(
    const float* __restrict__ Wq, const float* __restrict__ Wk,
    const float* __restrict__ Wv, const float* __restrict__ Wo)
{
    const int osel = blockIdx.z;
    const float* x = (osel == 0) ? Wq : (osel == 1) ? Wk : (osel == 2) ? Wv : Wo;
    __nv_bfloat16* y = (osel == 0) ? g_WTq : (osel == 1) ? g_WTk
                     : (osel == 2) ? g_WTv : g_WTo;

    __shared__ float t[32][33];
    const int c0 = blockIdx.x * 32, r0 = blockIdx.y * 32;
    const int tx = threadIdx.x, ty = threadIdx.y;

#pragma unroll
    for (int i = 0; i < 4; i++)
        t[ty + 8 * i][tx] = x[(size_t)(r0 + ty + 8 * i) * KK + c0 + tx];
    __syncthreads();
#pragma unroll
    for (int i = 0; i < 4; i++)
        y[(size_t)(c0 + ty + 8 * i) * KK + r0 + tx] = __float2bfloat16(t[tx][ty + 8 * i]);
}

// ---------------------------------------------------------------------------
// fp32 -> bf16 convert (activations); out selected device-side
// ---------------------------------------------------------------------------
__global__ __launch_bounds__(256) void c2bf(const float* __restrict__ x, int osel)
{
    __nv_bfloat16* y = (osel == 0) ? g_Aq : g_Akv;
    int i = blockIdx.x * 256 + threadIdx.x;
    float4 v = ((const float4*)x)[i];
    ((uint32_t*)y)[2 * i]     = pack_bf2(v.x, v.y);
    ((uint32_t*)y)[2 * i + 1] = pack_bf2(v.z, v.w);
}

// ---------------------------------------------------------------------------
// bf16 tensor-core flash attention.
// Block: 128 q-rows of one (b,h), 256 thr / 8 warps x 16 q-rows. KV tile 64.
// K smem [kv][hd] bf16, VT smem [hd][kv] bf16 (both 36-uint stride).
// PV A-fragments come straight from S C-fragments (no shuffles!).
// ---------------------------------------------------------------------------
#define ASTR 36

__global__ __launch_bounds__(256, 1) void attn_tc()
{
    __shared__ uint32_t sK[64 * ASTR];
    __shared__ uint32_t sVT[64 * ASTR];

    const int bh = blockIdx.y;
    const int q0 = blockIdx.x * 128;
    const __nv_bfloat16* Qp  = g_Qh + (size_t)bh * LQ * HD;
    const __nv_bfloat16* Kp  = g_Kh + (size_t)bh * LKV * HD;
    const __nv_bfloat16* VTp = g_VT + (size_t)bh * 64 * LKV;

    const int tid  = threadIdx.x;
    const int lane = tid & 31;
    const int w    = tid >> 5;
    const int qr   = lane >> 2;
    const int qc   = lane & 3;

    // ---- Q fragments: 4 k16-steps x 4 regs (bf16x2 each) ----
    uint32_t qf[4][4];
    {
        const __nv_bfloat16* Qr0 = Qp + (size_t)(q0 + w * 16 + qr) * HD;
        const __nv_bfloat16* Qr1 = Qr0 + 8 * HD;
#pragma unroll
        for (int ks = 0; ks < 4; ks++) {
            int k = ks * 16 + qc * 2;
            qf[ks][0] = *(const uint32_t*)(Qr0 + k);
            qf[ks][1] = *(const uint32_t*)(Qr1 + k);
            qf[ks][2] = *(const uint32_t*)(Qr0 + k + 8);
            qf[ks][3] = *(const uint32_t*)(Qr1 + k + 8);
        }
    }

    float o[8][4];
#pragma unroll
    for (int i = 0; i < 8; i++)
#pragma unroll
        for (int j = 0; j < 4; j++) o[i][j] = 0.f;
    float m_i[2] = {-1e30f, -1e30f};
    float l_i[2] = {0.f, 0.f};

    for (int kv0 = 0; kv0 < LKV; kv0 += 64) {
        // stage K [64 kv][64 hd] and VT [64 hd][64 kv]: 8 chunks/row
#pragma unroll
        for (int i = 0; i < 2; i++) {
            int idx = tid + i * 256;
            int r = idx >> 3, ch = idx & 7;
            cp16(sK  + r * ASTR + ch * 4, Kp  + (size_t)(kv0 + r) * HD + ch * 8);
            cp16(sVT + r * ASTR + ch * 4, VTp + (size_t)r * LKV + kv0 + ch * 8);
        }
        CP_COMMIT();
        CP_WAIT0();
        __syncthreads();

        // ---- S = Q K^T : 4 ks x 8 nf mma ----
        float s[8][4];
#pragma unroll
        for (int i = 0; i < 8; i++)
#pragma unroll
            for (int j = 0; j < 4; j++) s[i][j] = 0.f;

#pragma unroll
        for (int ks = 0; ks < 4; ks++) {
            const int ko = ks * 8;
#pragma unroll
            for (int nf = 0; nf < 8; nf++) {
                int bb = (nf * 8 + qr) * ASTR + ko + qc;
                mma_bf16(s[nf], qf[ks][0], qf[ks][1], qf[ks][2], qf[ks][3],
                         sK[bb], sK[bb + 4]);
            }
        }

        // ---- online softmax (rows qr, qr+8; quad-shared) ----
        float mx0 = -1e30f, mx1 = -1e30f;
#pragma unroll
        for (int nf = 0; nf < 8; nf++) {
            s[nf][0] *= 0.125f; s[nf][1] *= 0.125f;
            s[nf][2] *= 0.125f; s[nf][3] *= 0.125f;
            mx0 = fmaxf(mx0, fmaxf(s[nf][0], s[nf][1]));
            mx1 = fmaxf(mx1, fmaxf(s[nf][2], s[nf][3]));
        }
        mx0 = fmaxf(mx0, __shfl_xor_sync(0xffffffffu, mx0, 1));
        mx0 = fmaxf(mx0, __shfl_xor_sync(0xffffffffu, mx0, 2));
        mx1 = fmaxf(mx1, __shfl_xor_sync(0xffffffffu, mx1, 1));
        mx1 = fmaxf(mx1, __shfl_xor_sync(0xffffffffu, mx1, 2));

        float mn0 = fmaxf(m_i[0], mx0), mn1 = fmaxf(m_i[1], mx1);
        float al0 = __expf(m_i[0] - mn0), al1 = __expf(m_i[1] - mn1);
        m_i[0] = mn0; m_i[1] = mn1;

        float rs0 = 0.f, rs1 = 0.f;
#pragma unroll
        for (int nf = 0; nf < 8; nf++) {
            s[nf][0] = __expf(s[nf][0] - mn0);
            s[nf][1] = __expf(s[nf][1] - mn0);
            s[nf][2] = __expf(s[nf][2] - mn1);
            s[nf][3] = __expf(s[nf][3] - mn1);
            rs0 += s[nf][0] + s[nf][1];
            rs1 += s[nf][2] + s[nf][3];
        }
        rs0 += __shfl_xor_sync(0xffffffffu, rs0, 1);
        rs0 += __shfl_xor_sync(0xffffffffu, rs0, 2);
        rs1 += __shfl_xor_sync(0xffffffffu, rs1, 1);
        rs1 += __shfl_xor_sync(0xffffffffu, rs1, 2);
        l_i[0] = l_i[0] * al0 + rs0;
        l_i[1] = l_i[1] * al1 + rs1;

#pragma unroll
        for (int nf = 0; nf < 8; nf++) {
            o[nf][0] *= al0; o[nf][1] *= al0;
            o[nf][2] *= al1; o[nf][3] *= al1;
        }

        // ---- O += P V : A-frags = packed S C-frags (layout identity) ----
#pragma unroll
        for (int kg = 0; kg < 4; kg++) {
            uint32_t a0 = pack_bf2(s[2 * kg][0],     s[2 * kg][1]);
            uint32_t a1 = pack_bf2(s[2 * kg][2],     s[2 * kg][3]);
            uint32_t a2 = pack_bf2(s[2 * kg + 1][0], s[2 * kg + 1][1]);
            uint32_t a3 = pack_bf2(s[2 * kg + 1][2], s[2 * kg + 1][3]);
            const int ko = kg * 8;
#pragma unroll
            for (int nf = 0; nf < 8; nf++) {
                int bb = (nf * 8 + qr) * ASTR + ko + qc;
                mma_bf16(o[nf], a0, a1, a2, a3, sVT[bb], sVT[bb + 4]);
            }
        }
        __syncthreads();
    }

    // ---- epilogue: O / l -> g_ctxh (bf16, interleaved layout) ----
    const int b = bh >> 4, h = bh & 15;
    const float inv0 = 1.0f / l_i[0], inv1 = 1.0f / l_i[1];
    const int r0 = q0 + w * 16 + qr;
#pragma unroll
    for (int nf = 0; nf < 8; nf++) {
        int col = h * HD + nf * 8 + qc * 2;
        *(uint32_t*)(g_ctxh + (size_t)(b * LQ + r0) * D + col)
            = pack_bf2(o[nf][0] * inv0, o[nf][1] * inv0);
        *(uint32_t*)(g_ctxh + (size_t)(b * LQ + r0 + 8) * D + col)
            = pack_bf2(o[nf][2] * inv1, o[nf][3] * inv1);
    }
}

// ---------------------------------------------------------------------------
// LayerNorm over last dim (1024)
// ---------------------------------------------------------------------------
__global__ __launch_bounds__(256) void ln_kernel(
    const float* __restrict__ gamma, const float* __restrict__ beta,
    float* __restrict__ out)
{
    __shared__ float red[8];
    const int row = blockIdx.x;
    const int t   = threadIdx.x;
    const float* x = g_X + (size_t)row * D;

    float4 xv = *(const float4*)&x[t << 2];
    float s = xv.x + xv.y + xv.z + xv.w;
#pragma unroll
    for (int m = 16; m > 0; m >>= 1) s += __shfl_xor_sync(0xffffffffu, s, m);
    if ((t & 31) == 0) red[t >> 5] = s;
    __syncthreads();
    float tot = 0.f;
#pragma unroll
    for (int i = 0; i < 8; i++) tot += red[i];
    float mu = tot * (1.0f / D);

    float d0 = xv.x - mu, d1 = xv.y - mu, d2 = xv.z - mu, d3 = xv.w - mu;
    float ss = d0 * d0 + d1 * d1 + d2 * d2 + d3 * d3;
#pragma unroll
    for (int m = 16; m > 0; m >>= 1) ss += __shfl_xor_sync(0xffffffffu, ss, m);
    __syncthreads();
    if ((t & 31) == 0) red[t >> 5] = ss;
    __syncthreads();
    float vtot = 0.f;
#pragma unroll
    for (int i = 0; i < 8; i++) vtot += red[i];
    float inv = rsqrtf(vtot * (1.0f / D) + EPS);

    float4 g  = *(const float4*)&gamma[t << 2];
    float4 be = *(const float4*)&beta[t << 2];
    float4 o;
    o.x = d0 * inv * g.x + be.x;
    o.y = d1 * inv * g.y + be.y;
    o.z = d2 * inv * g.z + be.z;
    o.w = d3 * inv * g.w + be.w;
    *(float4*)&out[(size_t)row * D + (t << 2)] = o;
}

// ---------------------------------------------------------------------------
extern "C" void kernel_launch(void* const* d_in, const int* in_sizes, int n_in,
                              void* d_out, int out_size)
{
    (void)in_sizes; (void)n_in; (void)out_size;
    const float* query     = (const float*)d_in[0];
    const float* key_value = (const float*)d_in[1];
    const float* Wq = (const float*)d_in[2];
    const float* bq = (const float*)d_in[3];
    const float* Wk = (const float*)d_in[4];
    const float* bk = (const float*)d_in[5];
    const float* Wv = (const float*)d_in[6];
    const float* bv = (const float*)d_in[7];
    const float* Wo = (const float*)d_in[8];
    const float* bo = (const float*)d_in[9];
    const float* gamma = (const float*)d_in[10];
    const float* beta  = (const float*)d_in[11];
    float* out = (float*)d_out;

    // 1. weights: transpose + bf16
    wtrans4<<<dim3(32, 32, 4), dim3(32, 8)>>>(Wq, Wk, Wv, Wo);

    // 2. activations: fp32 -> bf16
    c2bf<<<QSZ / 1024, 256>>>(query,     0);
    c2bf<<<QSZ / 1024, 256>>>(key_value, 1);

    // 3. Q/K/V projections (bf16 mma): Q,K head-major; V transposed
    dim3 pg(8, 32);
    tgemm<0><<<pg, 256>>>(0, 0, bq, nullptr);
    tgemm<0><<<pg, 256>>>(1, 1, bk, nullptr);
    tgemm<0><<<pg, 256>>>(1, 2, bv, nullptr);

    // 4. attention (bf16 tensor-core flash)
    attn_tc<<<dim3(LQ / 128, LBH), 256>>>();

    // 5. output projection + residual (bf16 mma, fp32 out)
    tgemm<1><<<pg, 256>>>(0, 3, bo, query);

    // 6. LayerNorm
    ln_kernel<<<MTOT, 256>>>(gamma, beta, out);
}

// round 13
// speedup vs baseline: 2.6805x; 1.3649x over previous
#include <cuda_runtime.h>
#include <cuda_bf16.h>
#include <cstdint>

#define B_   2
#define LQ   2048
#define LKV  2048
#define D    1024
#define NH   16
#define HD   64
#define MTOT (B_ * LQ)
#define LBH  (B_ * NH)
#define EPS  1e-5f
#define QSZ  4194304           // 4096*1024

// ---------------------------------------------------------------------------
// Scratch (static __device__, allocation-free).
// RULE (learned R3-R6): NEVER pass these as kernel arguments from host —
// host sees the shadow symbol, and GB300 ATS silently dereferences it.
// ---------------------------------------------------------------------------
__device__ __nv_bfloat16 g_WTq[1048576], g_WTk[1048576], g_WTv[1048576], g_WTo[1048576];
__device__ __nv_bfloat16 g_Aq[QSZ], g_Akv[QSZ];     // bf16 activations
__device__ __nv_bfloat16 g_Qh[QSZ], g_Kh[QSZ];      // head-major Q,K bf16
__device__ __nv_bfloat16 g_VT[QSZ];                 // V transposed per head [bh][hd][kv]
__device__ __nv_bfloat16 g_ctxh[QSZ];               // ctx bf16
__device__ float g_X[QSZ];                          // pre-LN fp32

// ---------------------------------------------------------------------------
// helpers
// ---------------------------------------------------------------------------
__device__ __forceinline__ void cp16(void* s, const void* g) {
    uint32_t sa;
    asm("{ .reg .u64 t; cvta.to.shared.u64 t, %1; cvt.u32.u64 %0, t; }"
        : "=r"(sa) : "l"(s));
    asm volatile("cp.async.cg.shared.global [%0], [%1], 16;" :: "r"(sa), "l"(g) : "memory");
}
#define CP_COMMIT()  asm volatile("cp.async.commit_group;" ::: "memory")
#define CP_WAIT0()   asm volatile("cp.async.wait_group 0;" ::: "memory")

// pack two fp32 into bf16x2: result = {lo, hi}
__device__ __forceinline__ uint32_t pack_bf2(float lo, float hi) {
    uint32_t r;
    asm("cvt.rn.bf16x2.f32 %0, %1, %2;" : "=r"(r) : "f"(hi), "f"(lo));
    return r;
}

__device__ __forceinline__ void mma_bf16(float* c, uint32_t a0, uint32_t a1,
                                         uint32_t a2, uint32_t a3,
                                         uint32_t b0, uint32_t b1) {
    asm volatile(
        "mma.sync.aligned.m16n8k16.row.col.f32.bf16.bf16.f32 "
        "{%0,%1,%2,%3},{%4,%5,%6,%7},{%8,%9},{%0,%1,%2,%3};"
        : "+f"(c[0]), "+f"(c[1]), "+f"(c[2]), "+f"(c[3])
        : "r"(a0), "r"(a1), "r"(a2), "r"(a3), "r"(b0), "r"(b1));
}

// ---------------------------------------------------------------------------
// bf16 warp-MMA GEMM: C[M,1024] = A @ W  (A bf16 scratch, WT[N,K] bf16).
// Block 128x128, BK=64, 256 thr, warp tile 64x32, single-buffered cp.async.
// __launch_bounds__(256,2): 2 CTAs/SM -> inter-CTA load/MMA overlap.
// E=0: grid.z selects Q/K/V (A and bias chosen device-side)
// E=1: A = g_ctxh; X = A @ Wo + bias + resid -> g_X (fp32)
// ---------------------------------------------------------------------------
#define KK 1024
#define GSTR 36               // uint stride per row (64 bf16 = 32 uint + 4 pad)

template <int E>
__global__ __launch_bounds__(256, 2) void tgemm(
    const float* __restrict__ bias0, const float* __restrict__ bias1,
    const float* __restrict__ bias2, const float* __restrict__ resid)
{
    __shared__ uint32_t sA[128 * GSTR];
    __shared__ uint32_t sB[128 * GSTR];

    const int sel = (E == 0) ? (int)blockIdx.z : 3;
    const __nv_bfloat16* B = (sel == 0) ? g_WTq : (sel == 1) ? g_WTk
                           : (sel == 2) ? g_WTv : g_WTo;
    const __nv_bfloat16* A = (E == 1) ? g_ctxh : (sel == 0 ? g_Aq : g_Akv);
    const float* bias = (E == 1) ? bias0
                      : (sel == 0) ? bias0 : (sel == 1) ? bias1 : bias2;

    const int tid  = threadIdx.x;
    const int lane = tid & 31;
    const int w    = tid >> 5;
    const int wm   = w & 1;
    const int wn   = w >> 1;
    const int m0 = blockIdx.y * 128, n0 = blockIdx.x * 128;
    const int qr = lane >> 2, qc = lane & 3;

    float c[4][4][4];
#pragma unroll
    for (int i = 0; i < 4; i++)
#pragma unroll
        for (int j = 0; j < 4; j++)
#pragma unroll
            for (int q = 0; q < 4; q++) c[i][j][q] = 0.f;

    const int arow = wm * 64 + qr;
    const int brow = wn * 32 + qr;

    for (int kb = 0; kb < KK; kb += 64) {
        // stage A,B: 128 rows x 64 bf16 = 8 chunks of 16B each
#pragma unroll
        for (int i = 0; i < 4; i++) {
            int idx = tid + i * 256;
            int r = idx >> 3, ch = idx & 7;
            int so = r * GSTR + ch * 4;
            cp16(sA + so, A + (size_t)(m0 + r) * KK + kb + ch * 8);
            cp16(sB + so, B + (size_t)(n0 + r) * KK + kb + ch * 8);
        }
        CP_COMMIT();
        CP_WAIT0();
        __syncthreads();

#pragma unroll
        for (int ks = 0; ks < 4; ks++) {         // 4 x k16 = 64
            const int ko = ks * 8;               // uint col
            uint32_t af[4][4], bf[4][2];
#pragma unroll
            for (int mf = 0; mf < 4; mf++) {
                int base = (arow + mf * 16) * GSTR + ko + qc;
                af[mf][0] = sA[base];
                af[mf][1] = sA[base + 8 * GSTR];
                af[mf][2] = sA[base + 4];
                af[mf][3] = sA[base + 8 * GSTR + 4];
            }
#pragma unroll
            for (int nf = 0; nf < 4; nf++) {
                int bb = (brow + nf * 8) * GSTR + ko + qc;
                bf[nf][0] = sB[bb];
                bf[nf][1] = sB[bb + 4];
            }
#pragma unroll
            for (int mf = 0; mf < 4; mf++)
#pragma unroll
                for (int nf = 0; nf < 4; nf++)
                    mma_bf16(c[mf][nf], af[mf][0], af[mf][1], af[mf][2], af[mf][3],
                             bf[nf][0], bf[nf][1]);
        }
        __syncthreads();
    }

    // ---- epilogue ----
#pragma unroll
    for (int mf = 0; mf < 4; mf++)
#pragma unroll
        for (int nf = 0; nf < 4; nf++)
#pragma unroll
            for (int half = 0; half < 2; half++) {
                int m = m0 + wm * 64 + mf * 16 + qr + half * 8;
                int n = n0 + wn * 32 + nf * 8 + qc * 2;
                float vx = c[mf][nf][half * 2]     + __ldg(&bias[n]);
                float vy = c[mf][nf][half * 2 + 1] + __ldg(&bias[n + 1]);

                if constexpr (E == 0) {
                    int bh = (m >> 11) * NH + (n >> 6);
                    int l  = m & 2047;
                    int hd = n & 63;
                    if (sel == 2) {
                        // V: transposed scatter -> g_VT[bh][hd][kv]
                        g_VT[((size_t)bh * 64 + hd) * LKV + l]     = __float2bfloat16(vx);
                        g_VT[((size_t)bh * 64 + hd + 1) * LKV + l] = __float2bfloat16(vy);
                    } else {
                        __nv_bfloat16* outp = (sel == 0) ? g_Qh : g_Kh;
                        *(uint32_t*)(outp + ((size_t)bh * LQ + l) * HD + hd) = pack_bf2(vx, vy);
                    }
                } else {
                    size_t idx = (size_t)m * D + n;
                    float2 r4 = *(const float2*)(resid + idx);
                    *(float2*)(g_X + idx) = make_float2(vx + r4.x, vy + r4.y);
                }
            }
}

// ---------------------------------------------------------------------------
// transpose + fp32->bf16: harness W[K,N] -> g_WT*[N,K] bf16 (device-side sel)
// ---------------------------------------------------------------------------
__global__ __launch_bounds__(256) void wtrans4(
    const float* __restrict__ Wq, const float* __restrict__ Wk,
    const float* __restrict__ Wv, const float* __restrict__ Wo)
{
    const int osel = blockIdx.z;
    const float* x = (osel == 0) ? Wq : (osel == 1) ? Wk : (osel == 2) ? Wv : Wo;
    __nv_bfloat16* y = (osel == 0) ? g_WTq : (osel == 1) ? g_WTk
                     : (osel == 2) ? g_WTv : g_WTo;

    __shared__ float t[32][33];
    const int c0 = blockIdx.x * 32, r0 = blockIdx.y * 32;
    const int tx = threadIdx.x, ty = threadIdx.y;

#pragma unroll
    for (int i = 0; i < 4; i++)
        t[ty + 8 * i][tx] = x[(size_t)(r0 + ty + 8 * i) * KK + c0 + tx];
    __syncthreads();
#pragma unroll
    for (int i = 0; i < 4; i++)
        y[(size_t)(c0 + ty + 8 * i) * KK + r0 + tx] = __float2bfloat16(t[tx][ty + 8 * i]);
}

// ---------------------------------------------------------------------------
// fp32 -> bf16 convert (activations); out selected device-side
// ---------------------------------------------------------------------------
__global__ __launch_bounds__(256) void c2bf(const float* __restrict__ x, int osel)
{
    __nv_bfloat16* y = (osel == 0) ? g_Aq : g_Akv;
    int i = blockIdx.x * 256 + threadIdx.x;
    float4 v = ((const float4*)x)[i];
    ((uint32_t*)y)[2 * i]     = pack_bf2(v.x, v.y);
    ((uint32_t*)y)[2 * i + 1] = pack_bf2(v.z, v.w);
}

// ---------------------------------------------------------------------------
// bf16 tensor-core flash attention (2 CTAs/SM).
// Block: 128 q-rows of one (b,h), 256 thr / 8 warps x 16 q-rows. KV tile 64.
// K smem [kv][hd] bf16, VT smem [hd][kv] bf16 (both 36-uint stride).
// PV A-fragments come straight from S C-fragments (no shuffles).
// ---------------------------------------------------------------------------
#define ASTR 36

__global__ __launch_bounds__(256, 2) void attn_tc()
{
    __shared__ uint32_t sK[64 * ASTR];
    __shared__ uint32_t sVT[64 * ASTR];

    const int bh = blockIdx.y;
    const int q0 = blockIdx.x * 128;
    const __nv_bfloat16* Qp  = g_Qh + (size_t)bh * LQ * HD;
    const __nv_bfloat16* Kp  = g_Kh + (size_t)bh * LKV * HD;
    const __nv_bfloat16* VTp = g_VT + (size_t)bh * 64 * LKV;

    const int tid  = threadIdx.x;
    const int lane = tid & 31;
    const int w    = tid >> 5;
    const int qr   = lane >> 2;
    const int qc   = lane & 3;

    // ---- Q fragments: 4 k16-steps x 4 regs (bf16x2 each) ----
    uint32_t qf[4][4];
    {
        const __nv_bfloat16* Qr0 = Qp + (size_t)(q0 + w * 16 + qr) * HD;
        const __nv_bfloat16* Qr1 = Qr0 + 8 * HD;
#pragma unroll
        for (int ks = 0; ks < 4; ks++) {
            int k = ks * 16 + qc * 2;
            qf[ks][0] = *(const uint32_t*)(Qr0 + k);
            qf[ks][1] = *(const uint32_t*)(Qr1 + k);
            qf[ks][2] = *(const uint32_t*)(Qr0 + k + 8);
            qf[ks][3] = *(const uint32_t*)(Qr1 + k + 8);
        }
    }

    float o[8][4];
#pragma unroll
    for (int i = 0; i < 8; i++)
#pragma unroll
        for (int j = 0; j < 4; j++) o[i][j] = 0.f;
    float m_i[2] = {-1e30f, -1e30f};
    float l_i[2] = {0.f, 0.f};

    for (int kv0 = 0; kv0 < LKV; kv0 += 64) {
        // stage K [64 kv][64 hd] and VT [64 hd][64 kv]: 8 chunks/row
#pragma unroll
        for (int i = 0; i < 2; i++) {
            int idx = tid + i * 256;
            int r = idx >> 3, ch = idx & 7;
            cp16(sK  + r * ASTR + ch * 4, Kp  + (size_t)(kv0 + r) * HD + ch * 8);
            cp16(sVT + r * ASTR + ch * 4, VTp + (size_t)r * LKV + kv0 + ch * 8);
        }
        CP_COMMIT();
        CP_WAIT0();
        __syncthreads();

        // ---- S = Q K^T : 4 ks x 8 nf mma ----
        float s[8][4];
#pragma unroll
        for (int i = 0; i < 8; i++)
#pragma unroll
            for (int j = 0; j < 4; j++) s[i][j] = 0.f;

#pragma unroll
        for (int ks = 0; ks < 4; ks++) {
            const int ko = ks * 8;
#pragma unroll
            for (int nf = 0; nf < 8; nf++) {
                int bb = (nf * 8 + qr) * ASTR + ko + qc;
                mma_bf16(s[nf], qf[ks][0], qf[ks][1], qf[ks][2], qf[ks][3],
                         sK[bb], sK[bb + 4]);
            }
        }

        // ---- online softmax (rows qr, qr+8; quad-shared) ----
        float mx0 = -1e30f, mx1 = -1e30f;
#pragma unroll
        for (int nf = 0; nf < 8; nf++) {
            s[nf][0] *= 0.125f; s[nf][1] *= 0.125f;
            s[nf][2] *= 0.125f; s[nf][3] *= 0.125f;
            mx0 = fmaxf(mx0, fmaxf(s[nf][0], s[nf][1]));
            mx1 = fmaxf(mx1, fmaxf(s[nf][2], s[nf][3]));
        }
        mx0 = fmaxf(mx0, __shfl_xor_sync(0xffffffffu, mx0, 1));
        mx0 = fmaxf(mx0, __shfl_xor_sync(0xffffffffu, mx0, 2));
        mx1 = fmaxf(mx1, __shfl_xor_sync(0xffffffffu, mx1, 1));
        mx1 = fmaxf(mx1, __shfl_xor_sync(0xffffffffu, mx1, 2));

        float mn0 = fmaxf(m_i[0], mx0), mn1 = fmaxf(m_i[1], mx1);
        float al0 = __expf(m_i[0] - mn0), al1 = __expf(m_i[1] - mn1);
        m_i[0] = mn0; m_i[1] = mn1;

        float rs0 = 0.f, rs1 = 0.f;
#pragma unroll
        for (int nf = 0; nf < 8; nf++) {
            s[nf][0] = __expf(s[nf][0] - mn0);
            s[nf][1] = __expf(s[nf][1] - mn0);
            s[nf][2] = __expf(s[nf][2] - mn1);
            s[nf][3] = __expf(s[nf][3] - mn1);
            rs0 += s[nf][0] + s[nf][1];
            rs1 += s[nf][2] + s[nf][3];
        }
        rs0 += __shfl_xor_sync(0xffffffffu, rs0, 1);
        rs0 += __shfl_xor_sync(0xffffffffu, rs0, 2);
        rs1 += __shfl_xor_sync(0xffffffffu, rs1, 1);
        rs1 += __shfl_xor_sync(0xffffffffu, rs1, 2);
        l_i[0] = l_i[0] * al0 + rs0;
        l_i[1] = l_i[1] * al1 + rs1;

#pragma unroll
        for (int nf = 0; nf < 8; nf++) {
            o[nf][0] *= al0; o[nf][1] *= al0;
            o[nf][2] *= al1; o[nf][3] *= al1;
        }

        // ---- O += P V : A-frags = packed S C-frags (layout identity) ----
#pragma unroll
        for (int kg = 0; kg < 4; kg++) {
            uint32_t a0 = pack_bf2(s[2 * kg][0],     s[2 * kg][1]);
            uint32_t a1 = pack_bf2(s[2 * kg][2],     s[2 * kg][3]);
            uint32_t a2 = pack_bf2(s[2 * kg + 1][0], s[2 * kg + 1][1]);
            uint32_t a3 = pack_bf2(s[2 * kg + 1][2], s[2 * kg + 1][3]);
            const int ko = kg * 8;
#pragma unroll
            for (int nf = 0; nf < 8; nf++) {
                int bb = (nf * 8 + qr) * ASTR + ko + qc;
                mma_bf16(o[nf], a0, a1, a2, a3, sVT[bb], sVT[bb + 4]);
            }
        }
        __syncthreads();
    }

    // ---- epilogue: O / l -> g_ctxh (bf16, interleaved layout) ----
    const int b = bh >> 4, h = bh & 15;
    const float inv0 = 1.0f / l_i[0], inv1 = 1.0f / l_i[1];
    const int r0 = q0 + w * 16 + qr;
#pragma unroll
    for (int nf = 0; nf < 8; nf++) {
        int col = h * HD + nf * 8 + qc * 2;
        *(uint32_t*)(g_ctxh + (size_t)(b * LQ + r0) * D + col)
            = pack_bf2(o[nf][0] * inv0, o[nf][1] * inv0);
        *(uint32_t*)(g_ctxh + (size_t)(b * LQ + r0 + 8) * D + col)
            = pack_bf2(o[nf][2] * inv1, o[nf][3] * inv1);
    }
}

// ---------------------------------------------------------------------------
// LayerNorm over last dim (1024)
// ---------------------------------------------------------------------------
__global__ __launch_bounds__(256) void ln_kernel(
    const float* __restrict__ gamma, const float* __restrict__ beta,
    float* __restrict__ out)
{
    __shared__ float red[8];
    const int row = blockIdx.x;
    const int t   = threadIdx.x;
    const float* x = g_X + (size_t)row * D;

    float4 xv = *(const float4*)&x[t << 2];
    float s = xv.x + xv.y + xv.z + xv.w;
#pragma unroll
    for (int m = 16; m > 0; m >>= 1) s += __shfl_xor_sync(0xffffffffu, s, m);
    if ((t & 31) == 0) red[t >> 5] = s;
    __syncthreads();
    float tot = 0.f;
#pragma unroll
    for (int i = 0; i < 8; i++) tot += red[i];
    float mu = tot * (1.0f / D);

    float d0 = xv.x - mu, d1 = xv.y - mu, d2 = xv.z - mu, d3 = xv.w - mu;
    float ss = d0 * d0 + d1 * d1 + d2 * d2 + d3 * d3;
#pragma unroll
    for (int m = 16; m > 0; m >>= 1) ss += __shfl_xor_sync(0xffffffffu, ss, m);
    __syncthreads();
    if ((t & 31) == 0) red[t >> 5] = ss;
    __syncthreads();
    float vtot = 0.f;
#pragma unroll
    for (int i = 0; i < 8; i++) vtot += red[i];
    float inv = rsqrtf(vtot * (1.0f / D) + EPS);

    float4 g  = *(const float4*)&gamma[t << 2];
    float4 be = *(const float4*)&beta[t << 2];
    float4 o;
    o.x = d0 * inv * g.x + be.x;
    o.y = d1 * inv * g.y + be.y;
    o.z = d2 * inv * g.z + be.z;
    o.w = d3 * inv * g.w + be.w;
    *(float4*)&out[(size_t)row * D + (t << 2)] = o;
}

// ---------------------------------------------------------------------------
extern "C" void kernel_launch(void* const* d_in, const int* in_sizes, int n_in,
                              void* d_out, int out_size)
{
    (void)in_sizes; (void)n_in; (void)out_size;
    const float* query     = (const float*)d_in[0];
    const float* key_value = (const float*)d_in[1];
    const float* Wq = (const float*)d_in[2];
    const float* bq = (const float*)d_in[3];
    const float* Wk = (const float*)d_in[4];
    const float* bk = (const float*)d_in[5];
    const float* Wv = (const float*)d_in[6];
    const float* bv = (const float*)d_in[7];
    const float* Wo = (const float*)d_in[8];
    const float* bo = (const float*)d_in[9];
    const float* gamma = (const float*)d_in[10];
    const float* beta  = (const float*)d_in[11];
    float* out = (float*)d_out;

    // 1. weights: transpose + bf16
    wtrans4<<<dim3(32, 32, 4), dim3(32, 8)>>>(Wq, Wk, Wv, Wo);

    // 2. activations: fp32 -> bf16
    c2bf<<<QSZ / 1024, 256>>>(query,     0);
    c2bf<<<QSZ / 1024, 256>>>(key_value, 1);

    // 3. Q/K/V projections in ONE launch (grid.z selects target)
    tgemm<0><<<dim3(8, 32, 3), 256>>>(bq, bk, bv, nullptr);

    // 4. attention (bf16 tensor-core flash, 2 CTAs/SM)
    attn_tc<<<dim3(LQ / 128, LBH), 256>>>();

    // 5. output projection + residual
    tgemm<1><<<dim3(8, 32, 1), 256>>>(bo, nullptr, nullptr, query);

    // 6. LayerNorm
    ln_kernel<<<MTOT, 256>>>(gamma, beta, out);
}

// round 14
// speedup vs baseline: 2.8233x; 1.0533x over previous
#include <cuda_runtime.h>
#include <cuda_bf16.h>
#include <cstdint>

#define B_   2
#define LQ   2048
#define LKV  2048
#define D    1024
#define NH   16
#define HD   64
#define MTOT (B_ * LQ)
#define LBH  (B_ * NH)
#define EPS  1e-5f
#define QSZ  4194304           // 4096*1024

// ---------------------------------------------------------------------------
// Scratch (static __device__, allocation-free).
// RULE (learned R3-R6): NEVER pass these as kernel arguments from host.
// ---------------------------------------------------------------------------
__device__ __nv_bfloat16 g_WTq[1048576], g_WTk[1048576], g_WTv[1048576], g_WTo[1048576];
__device__ __nv_bfloat16 g_Aq[QSZ], g_Akv[QSZ];     // bf16 activations
__device__ __nv_bfloat16 g_Qh[QSZ], g_Kh[QSZ];      // head-major Q,K bf16
__device__ __nv_bfloat16 g_VT[QSZ];                 // V transposed per head [bh][hd][kv]
__device__ __nv_bfloat16 g_ctxh[QSZ];               // ctx bf16
__device__ float g_X[QSZ];                          // pre-LN fp32

// ---------------------------------------------------------------------------
// helpers
// ---------------------------------------------------------------------------
__device__ __forceinline__ void cp16(void* s, const void* g) {
    uint32_t sa;
    asm("{ .reg .u64 t; cvta.to.shared.u64 t, %1; cvt.u32.u64 %0, t; }"
        : "=r"(sa) : "l"(s));
    asm volatile("cp.async.cg.shared.global [%0], [%1], 16;" :: "r"(sa), "l"(g) : "memory");
}
#define CP_COMMIT()  asm volatile("cp.async.commit_group;" ::: "memory")
#define CP_WAIT0()   asm volatile("cp.async.wait_group 0;" ::: "memory")

__device__ __forceinline__ uint32_t s2u(const void* p) {
    uint32_t a;
    asm("{ .reg .u64 t; cvta.to.shared.u64 t, %1; cvt.u32.u64 %0, t; }"
        : "=r"(a) : "l"(p));
    return a;
}

#define LDSM4(r0, r1, r2, r3, addr) \
    asm volatile("ldmatrix.sync.aligned.m8n8.x4.shared.b16 {%0,%1,%2,%3}, [%4];" \
                 : "=r"(r0), "=r"(r1), "=r"(r2), "=r"(r3) : "r"(addr))

// pack two fp32 into bf16x2: result = {lo, hi}
__device__ __forceinline__ uint32_t pack_bf2(float lo, float hi) {
    uint32_t r;
    asm("cvt.rn.bf16x2.f32 %0, %1, %2;" : "=r"(r) : "f"(hi), "f"(lo));
    return r;
}

__device__ __forceinline__ void mma_bf16(float* c, uint32_t a0, uint32_t a1,
                                         uint32_t a2, uint32_t a3,
                                         uint32_t b0, uint32_t b1) {
    asm volatile(
        "mma.sync.aligned.m16n8k16.row.col.f32.bf16.bf16.f32 "
        "{%0,%1,%2,%3},{%4,%5,%6,%7},{%8,%9},{%0,%1,%2,%3};"
        : "+f"(c[0]), "+f"(c[1]), "+f"(c[2]), "+f"(c[3])
        : "r"(a0), "r"(a1), "r"(a2), "r"(a3), "r"(b0), "r"(b1));
}

// ---------------------------------------------------------------------------
// bf16 warp-MMA GEMM with ldmatrix fragment loads.
// Block 128x128, BK=64, 256 thr (8 warps, warp tile 64x32), 2 CTAs/SM.
// Per k16-step: 4 LDSM (A) + 2 LDSM (B) + 16 HMMA (was 24 LDS).
// ---------------------------------------------------------------------------
#define KK 1024
#define GSTR 36               // uint stride per row (64 bf16 = 32 uint + 4 pad)

template <int E>
__global__ __launch_bounds__(256, 2) void tgemm(
    const float* __restrict__ bias0, const float* __restrict__ bias1,
    const float* __restrict__ bias2, const float* __restrict__ resid)
{
    __shared__ __align__(16) uint32_t sA[128 * GSTR];
    __shared__ __align__(16) uint32_t sB[128 * GSTR];

    const int sel = (E == 0) ? (int)blockIdx.z : 3;
    const __nv_bfloat16* B = (sel == 0) ? g_WTq : (sel == 1) ? g_WTk
                           : (sel == 2) ? g_WTv : g_WTo;
    const __nv_bfloat16* A = (E == 1) ? g_ctxh : (sel == 0 ? g_Aq : g_Akv);
    const float* bias = (E == 1) ? bias0
                      : (sel == 0) ? bias0 : (sel == 1) ? bias1 : bias2;

    const int tid  = threadIdx.x;
    const int lane = tid & 31;
    const int w    = tid >> 5;
    const int wm   = w & 1;
    const int wn   = w >> 1;
    const int m0 = blockIdx.y * 128, n0 = blockIdx.x * 128;
    const int qr = lane >> 2, qc = lane & 3;

    float c[4][4][4];
#pragma unroll
    for (int i = 0; i < 4; i++)
#pragma unroll
        for (int j = 0; j < 4; j++)
#pragma unroll
            for (int q = 0; q < 4; q++) c[i][j][q] = 0.f;

    // ldmatrix per-lane base addresses (bytes, shared space)
    const uint32_t aBase = s2u(sA) +
        (((wm * 64 + (lane & 15)) * GSTR + (lane >> 4) * 4) << 2);
    const uint32_t bBase = s2u(sB) +
        (((wn * 32 + (lane & 7) + (lane >> 4) * 8) * GSTR + ((lane >> 3) & 1) * 4) << 2);

    for (int kb = 0; kb < KK; kb += 64) {
#pragma unroll
        for (int i = 0; i < 4; i++) {
            int idx = tid + i * 256;
            int r = idx >> 3, ch = idx & 7;
            int so = r * GSTR + ch * 4;
            cp16(sA + so, A + (size_t)(m0 + r) * KK + kb + ch * 8);
            cp16(sB + so, B + (size_t)(n0 + r) * KK + kb + ch * 8);
        }
        CP_COMMIT();
        CP_WAIT0();
        __syncthreads();

#pragma unroll
        for (int ks = 0; ks < 4; ks++) {         // 4 x k16 = 64
            uint32_t af[4][4], bf[4][2];
#pragma unroll
            for (int mf = 0; mf < 4; mf++)
                LDSM4(af[mf][0], af[mf][1], af[mf][2], af[mf][3],
                      aBase + ((mf * 16 * GSTR + ks * 8) << 2));
            LDSM4(bf[0][0], bf[0][1], bf[1][0], bf[1][1],
                  bBase + ((ks * 8) << 2));
            LDSM4(bf[2][0], bf[2][1], bf[3][0], bf[3][1],
                  bBase + ((16 * GSTR + ks * 8) << 2));
#pragma unroll
            for (int mf = 0; mf < 4; mf++)
#pragma unroll
                for (int nf = 0; nf < 4; nf++)
                    mma_bf16(c[mf][nf], af[mf][0], af[mf][1], af[mf][2], af[mf][3],
                             bf[nf][0], bf[nf][1]);
        }
        __syncthreads();
    }

    // ---- epilogue ----
#pragma unroll
    for (int mf = 0; mf < 4; mf++)
#pragma unroll
        for (int nf = 0; nf < 4; nf++)
#pragma unroll
            for (int half = 0; half < 2; half++) {
                int m = m0 + wm * 64 + mf * 16 + qr + half * 8;
                int n = n0 + wn * 32 + nf * 8 + qc * 2;
                float vx = c[mf][nf][half * 2]     + __ldg(&bias[n]);
                float vy = c[mf][nf][half * 2 + 1] + __ldg(&bias[n + 1]);

                if constexpr (E == 0) {
                    int bh = (m >> 11) * NH + (n >> 6);
                    int l  = m & 2047;
                    int hd = n & 63;
                    if (sel == 2) {
                        g_VT[((size_t)bh * 64 + hd) * LKV + l]     = __float2bfloat16(vx);
                        g_VT[((size_t)bh * 64 + hd + 1) * LKV + l] = __float2bfloat16(vy);
                    } else {
                        __nv_bfloat16* outp = (sel == 0) ? g_Qh : g_Kh;
                        *(uint32_t*)(outp + ((size_t)bh * LQ + l) * HD + hd) = pack_bf2(vx, vy);
                    }
                } else {
                    size_t idx = (size_t)m * D + n;
                    float2 r4 = *(const float2*)(resid + idx);
                    *(float2*)(g_X + idx) = make_float2(vx + r4.x, vy + r4.y);
                }
            }
}

// ---------------------------------------------------------------------------
// transpose + fp32->bf16: harness W[K,N] -> g_WT*[N,K] bf16 (device-side sel)
// ---------------------------------------------------------------------------
__global__ __launch_bounds__(256) void wtrans4(
    const float* __restrict__ Wq, const float* __restrict__ Wk,
    const float* __restrict__ Wv, const float* __restrict__ Wo)
{
    const int osel = blockIdx.z;
    const float* x = (osel == 0) ? Wq : (osel == 1) ? Wk : (osel == 2) ? Wv : Wo;
    __nv_bfloat16* y = (osel == 0) ? g_WTq : (osel == 1) ? g_WTk
                     : (osel == 2) ? g_WTv : g_WTo;

    __shared__ float t[32][33];
    const int c0 = blockIdx.x * 32, r0 = blockIdx.y * 32;
    const int tx = threadIdx.x, ty = threadIdx.y;

#pragma unroll
    for (int i = 0; i < 4; i++)
        t[ty + 8 * i][tx] = x[(size_t)(r0 + ty + 8 * i) * KK + c0 + tx];
    __syncthreads();
#pragma unroll
    for (int i = 0; i < 4; i++)
        y[(size_t)(c0 + ty + 8 * i) * KK + r0 + tx] = __float2bfloat16(t[tx][ty + 8 * i]);
}

// ---------------------------------------------------------------------------
// fp32 -> bf16 convert (activations); out selected device-side
// ---------------------------------------------------------------------------
__global__ __launch_bounds__(256) void c2bf(const float* __restrict__ x, int osel)
{
    __nv_bfloat16* y = (osel == 0) ? g_Aq : g_Akv;
    int i = blockIdx.x * 256 + threadIdx.x;
    float4 v = ((const float4*)x)[i];
    ((uint32_t*)y)[2 * i]     = pack_bf2(v.x, v.y);
    ((uint32_t*)y)[2 * i + 1] = pack_bf2(v.z, v.w);
}

// ---------------------------------------------------------------------------
// bf16 tensor-core flash attention, ldmatrix K/VT loads (2 CTAs/SM).
// Block: 128 q-rows of one (b,h), 256 thr / 8 warps x 16 q-rows. KV tile 64.
// ---------------------------------------------------------------------------
#define ASTR 36

__global__ __launch_bounds__(256, 2) void attn_tc()
{
    __shared__ __align__(16) uint32_t sK[64 * ASTR];
    __shared__ __align__(16) uint32_t sVT[64 * ASTR];

    const int bh = blockIdx.y;
    const int q0 = blockIdx.x * 128;
    const __nv_bfloat16* Qp  = g_Qh + (size_t)bh * LQ * HD;
    const __nv_bfloat16* Kp  = g_Kh + (size_t)bh * LKV * HD;
    const __nv_bfloat16* VTp = g_VT + (size_t)bh * 64 * LKV;

    const int tid  = threadIdx.x;
    const int lane = tid & 31;
    const int w    = tid >> 5;
    const int qr   = lane >> 2;
    const int qc   = lane & 3;

    // ---- Q fragments: 4 k16-steps x 4 regs (bf16x2 each) ----
    uint32_t qf[4][4];
    {
        const __nv_bfloat16* Qr0 = Qp + (size_t)(q0 + w * 16 + qr) * HD;
        const __nv_bfloat16* Qr1 = Qr0 + 8 * HD;
#pragma unroll
        for (int ks = 0; ks < 4; ks++) {
            int k = ks * 16 + qc * 2;
            qf[ks][0] = *(const uint32_t*)(Qr0 + k);
            qf[ks][1] = *(const uint32_t*)(Qr1 + k);
            qf[ks][2] = *(const uint32_t*)(Qr0 + k + 8);
            qf[ks][3] = *(const uint32_t*)(Qr1 + k + 8);
        }
    }

    // ldmatrix per-lane base addresses for K and VT (B-operand layout)
    const uint32_t kBase = s2u(sK) +
        ((((lane & 7) + (lane >> 4) * 8) * ASTR + ((lane >> 3) & 1) * 4) << 2);
    const uint32_t vBase = s2u(sVT) +
        ((((lane & 7) + (lane >> 4) * 8) * ASTR + ((lane >> 3) & 1) * 4) << 2);

    float o[8][4];
#pragma unroll
    for (int i = 0; i < 8; i++)
#pragma unroll
        for (int j = 0; j < 4; j++) o[i][j] = 0.f;
    float m_i[2] = {-1e30f, -1e30f};
    float l_i[2] = {0.f, 0.f};

    for (int kv0 = 0; kv0 < LKV; kv0 += 64) {
#pragma unroll
        for (int i = 0; i < 2; i++) {
            int idx = tid + i * 256;
            int r = idx >> 3, ch = idx & 7;
            cp16(sK  + r * ASTR + ch * 4, Kp  + (size_t)(kv0 + r) * HD + ch * 8);
            cp16(sVT + r * ASTR + ch * 4, VTp + (size_t)r * LKV + kv0 + ch * 8);
        }
        CP_COMMIT();
        CP_WAIT0();
        __syncthreads();

        // ---- S = Q K^T : per ks, 4 ldmatrix pairs + 8 mma ----
        float s[8][4];
#pragma unroll
        for (int i = 0; i < 8; i++)
#pragma unroll
            for (int j = 0; j < 4; j++) s[i][j] = 0.f;

#pragma unroll
        for (int ks = 0; ks < 4; ks++) {
#pragma unroll
            for (int p = 0; p < 4; p++) {
                uint32_t b00, b01, b10, b11;
                LDSM4(b00, b01, b10, b11,
                      kBase + ((p * 16 * ASTR + ks * 8) << 2));
                mma_bf16(s[2 * p],     qf[ks][0], qf[ks][1], qf[ks][2], qf[ks][3], b00, b01);
                mma_bf16(s[2 * p + 1], qf[ks][0], qf[ks][1], qf[ks][2], qf[ks][3], b10, b11);
            }
        }

        // ---- online softmax (rows qr, qr+8; quad-shared) ----
        float mx0 = -1e30f, mx1 = -1e30f;
#pragma unroll
        for (int nf = 0; nf < 8; nf++) {
            s[nf][0] *= 0.125f; s[nf][1] *= 0.125f;
            s[nf][2] *= 0.125f; s[nf][3] *= 0.125f;
            mx0 = fmaxf(mx0, fmaxf(s[nf][0], s[nf][1]));
            mx1 = fmaxf(mx1, fmaxf(s[nf][2], s[nf][3]));
        }
        mx0 = fmaxf(mx0, __shfl_xor_sync(0xffffffffu, mx0, 1));
        mx0 = fmaxf(mx0, __shfl_xor_sync(0xffffffffu, mx0, 2));
        mx1 = fmaxf(mx1, __shfl_xor_sync(0xffffffffu, mx1, 1));
        mx1 = fmaxf(mx1, __shfl_xor_sync(0xffffffffu, mx1, 2));

        float mn0 = fmaxf(m_i[0], mx0), mn1 = fmaxf(m_i[1], mx1);
        float al0 = __expf(m_i[0] - mn0), al1 = __expf(m_i[1] - mn1);
        m_i[0] = mn0; m_i[1] = mn1;

        float rs0 = 0.f, rs1 = 0.f;
#pragma unroll
        for (int nf = 0; nf < 8; nf++) {
            s[nf][0] = __expf(s[nf][0] - mn0);
            s[nf][1] = __expf(s[nf][1] - mn0);
            s[nf][2] = __expf(s[nf][2] - mn1);
            s[nf][3] = __expf(s[nf][3] - mn1);
            rs0 += s[nf][0] + s[nf][1];
            rs1 += s[nf][2] + s[nf][3];
        }
        rs0 += __shfl_xor_sync(0xffffffffu, rs0, 1);
        rs0 += __shfl_xor_sync(0xffffffffu, rs0, 2);
        rs1 += __shfl_xor_sync(0xffffffffu, rs1, 1);
        rs1 += __shfl_xor_sync(0xffffffffu, rs1, 2);
        l_i[0] = l_i[0] * al0 + rs0;
        l_i[1] = l_i[1] * al1 + rs1;

#pragma unroll
        for (int nf = 0; nf < 8; nf++) {
            o[nf][0] *= al0; o[nf][1] *= al0;
            o[nf][2] *= al1; o[nf][3] *= al1;
        }

        // ---- O += P V : A-frags = packed S C-frags; VT via ldmatrix ----
#pragma unroll
        for (int kg = 0; kg < 4; kg++) {
            uint32_t a0 = pack_bf2(s[2 * kg][0],     s[2 * kg][1]);
            uint32_t a1 = pack_bf2(s[2 * kg][2],     s[2 * kg][3]);
            uint32_t a2 = pack_bf2(s[2 * kg + 1][0], s[2 * kg + 1][1]);
            uint32_t a3 = pack_bf2(s[2 * kg + 1][2], s[2 * kg + 1][3]);
#pragma unroll
            for (int p = 0; p < 4; p++) {
                uint32_t b00, b01, b10, b11;
                LDSM4(b00, b01, b10, b11,
                      vBase + ((p * 16 * ASTR + kg * 8) << 2));
                mma_bf16(o[2 * p],     a0, a1, a2, a3, b00, b01);
                mma_bf16(o[2 * p + 1], a0, a1, a2, a3, b10, b11);
            }
        }
        __syncthreads();
    }

    // ---- epilogue: O / l -> g_ctxh (bf16, interleaved layout) ----
    const int b = bh >> 4, h = bh & 15;
    const float inv0 = 1.0f / l_i[0], inv1 = 1.0f / l_i[1];
    const int r0 = q0 + w * 16 + qr;
#pragma unroll
    for (int nf = 0; nf < 8; nf++) {
        int col = h * HD + nf * 8 + qc * 2;
        *(uint32_t*)(g_ctxh + (size_t)(b * LQ + r0) * D + col)
            = pack_bf2(o[nf][0] * inv0, o[nf][1] * inv0);
        *(uint32_t*)(g_ctxh + (size_t)(b * LQ + r0 + 8) * D + col)
            = pack_bf2(o[nf][2] * inv1, o[nf][3] * inv1);
    }
}

// ---------------------------------------------------------------------------
// LayerNorm over last dim (1024)
// ---------------------------------------------------------------------------
__global__ __launch_bounds__(256) void ln_kernel(
    const float* __restrict__ gamma, const float* __restrict__ beta,
    float* __restrict__ out)
{
    __shared__ float red[8];
    const int row = blockIdx.x;
    const int t   = threadIdx.x;
    const float* x = g_X + (size_t)row * D;

    float4 xv = *(const float4*)&x[t << 2];
    float s = xv.x + xv.y + xv.z + xv.w;
#pragma unroll
    for (int m = 16; m > 0; m >>= 1) s += __shfl_xor_sync(0xffffffffu, s, m);
    if ((t & 31) == 0) red[t >> 5] = s;
    __syncthreads();
    float tot = 0.f;
#pragma unroll
    for (int i = 0; i < 8; i++) tot += red[i];
    float mu = tot * (1.0f / D);

    float d0 = xv.x - mu, d1 = xv.y - mu, d2 = xv.z - mu, d3 = xv.w - mu;
    float ss = d0 * d0 + d1 * d1 + d2 * d2 + d3 * d3;
#pragma unroll
    for (int m = 16; m > 0; m >>= 1) ss += __shfl_xor_sync(0xffffffffu, ss, m);
    __syncthreads();
    if ((t & 31) == 0) red[t >> 5] = ss;
    __syncthreads();
    float vtot = 0.f;
#pragma unroll
    for (int i = 0; i < 8; i++) vtot += red[i];
    float inv = rsqrtf(vtot * (1.0f / D) + EPS);

    float4 g  = *(const float4*)&gamma[t << 2];
    float4 be = *(const float4*)&beta[t << 2];
    float4 o;
    o.x = d0 * inv * g.x + be.x;
    o.y = d1 * inv * g.y + be.y;
    o.z = d2 * inv * g.z + be.z;
    o.w = d3 * inv * g.w + be.w;
    *(float4*)&out[(size_t)row * D + (t << 2)] = o;
}

// ---------------------------------------------------------------------------
extern "C" void kernel_launch(void* const* d_in, const int* in_sizes, int n_in,
                              void* d_out, int out_size)
{
    (void)in_sizes; (void)n_in; (void)out_size;
    const float* query     = (const float*)d_in[0];
    const float* key_value = (const float*)d_in[1];
    const float* Wq = (const float*)d_in[2];
    const float* bq = (const float*)d_in[3];
    const float* Wk = (const float*)d_in[4];
    const float* bk = (const float*)d_in[5];
    const float* Wv = (const float*)d_in[6];
    const float* bv = (const float*)d_in[7];
    const float* Wo = (const float*)d_in[8];
    const float* bo = (const float*)d_in[9];
    const float* gamma = (const float*)d_in[10];
    const float* beta  = (const float*)d_in[11];
    float* out = (float*)d_out;

    // 1. weights: transpose + bf16
    wtrans4<<<dim3(32, 32, 4), dim3(32, 8)>>>(Wq, Wk, Wv, Wo);

    // 2. activations: fp32 -> bf16
    c2bf<<<QSZ / 1024, 256>>>(query,     0);
    c2bf<<<QSZ / 1024, 256>>>(key_value, 1);

    // 3. Q/K/V projections in ONE launch (grid.z selects target)
    tgemm<0><<<dim3(8, 32, 3), 256>>>(bq, bk, bv, nullptr);

    // 4. attention (bf16 tensor-core flash, ldmatrix, 2 CTAs/SM)
    attn_tc<<<dim3(LQ / 128, LBH), 256>>>();

    // 5. output projection + residual
    tgemm<1><<<dim3(8, 32, 1), 256>>>(bo, nullptr, nullptr, query);

    // 6. LayerNorm
    ln_kernel<<<MTOT, 256>>>(gamma, beta, out);
}